// round 3
// baseline (speedup 1.0000x reference)
#include <cuda_runtime.h>
#include <cstdint>

#define M_NODES 200000
#define NDIM    128
#define GDIM    128
#define HIDDEN  512
#define NGRAPH  1024
#define N1      1024   // combined hidden width: 512 (i-path) + 512 (j-path)

#define BM 128
#define BN 128
#define BK 16
#define TM 8
#define TN 8
#define NTHREADS 256

// Scratch for first-layer activations: Y[m][0:512]=relu(X@Wi1+bi1), Y[m][512:1024]=relu(hT@Wj1+bj1)
__device__ float g_Y[(size_t)M_NODES * N1];

// ---------- packed f32x2 helpers (sm_103a FFMA2 path) ----------
__device__ __forceinline__ unsigned long long pack2(float lo, float hi) {
    unsigned long long r;
    unsigned int l = __float_as_uint(lo), h = __float_as_uint(hi);
    asm("mov.b64 %0, {%1, %2};" : "=l"(r) : "r"(l), "r"(h));
    return r;
}
__device__ __forceinline__ void unpack2(unsigned long long v, float &lo, float &hi) {
    unsigned int l, h;
    asm("mov.b64 {%0, %1}, %2;" : "=r"(l), "=r"(h) : "l"(v));
    lo = __uint_as_float(l); hi = __uint_as_float(h);
}
__device__ __forceinline__ unsigned long long ffma2(unsigned long long a,
                                                    unsigned long long b,
                                                    unsigned long long c) {
    unsigned long long d;
    asm("fma.rn.f32x2 %0, %1, %2, %3;" : "=l"(d) : "l"(a), "l"(b), "l"(c));
    return d;
}

// ---------- zero output ----------
__global__ void zero_out_kernel(float* __restrict__ R, int n) {
    int i = blockIdx.x * blockDim.x + threadIdx.x;
    if (i < n) R[i] = 0.0f;
}

// ---------- GEMM1: Y = relu([hT|h0] @ W1c + b1c) ----------
// grid.x tiles M, grid.y in [0,8): y<4 -> i-path (Wi1, K=256), y>=4 -> j-path (Wj1, K=128)
__global__ __launch_bounds__(NTHREADS)
void gemm1_kernel(const float* __restrict__ hT, const float* __restrict__ h0,
                  const float* __restrict__ Wi1, const float* __restrict__ bi1,
                  const float* __restrict__ Wj1, const float* __restrict__ bj1) {
    __shared__ float As[BK][BM + 4];
    __shared__ float Bs[BK][BN + 4];

    const int m0 = blockIdx.x * BM;
    const int n0 = blockIdx.y * BN;
    const bool jpath = (blockIdx.y >= 4);
    const int Kmax = jpath ? NDIM : (2 * NDIM);

    const int tid = threadIdx.x;
    const int tx = tid & 15;       // 0..15  (n direction)
    const int ty = tid >> 4;       // 0..15  (m direction)

    unsigned long long acc[TM][TN / 2];
    #pragma unroll
    for (int i = 0; i < TM; i++)
        #pragma unroll
        for (int j = 0; j < TN / 2; j++) acc[i][j] = 0ull;

    for (int kk = 0; kk < Kmax; kk += BK) {
        // --- load A tile (BM x BK), stored transposed As[k][m] ---
        #pragma unroll
        for (int r = 0; r < 2; r++) {
            int v = tid + r * NTHREADS;          // 0..511 float4 slots
            int row = v >> 2;                    // 0..127
            int kq  = (v & 3) * 4;               // 0,4,8,12
            int kg  = kk + kq;
            float4 a = make_float4(0.f, 0.f, 0.f, 0.f);
            int m = m0 + row;
            if (m < M_NODES) {
                const float* src = (kg < NDIM)
                    ? (hT + (size_t)m * NDIM + kg)
                    : (h0 + (size_t)m * NDIM + (kg - NDIM));
                a = *(const float4*)src;
            }
            As[kq + 0][row] = a.x;
            As[kq + 1][row] = a.y;
            As[kq + 2][row] = a.z;
            As[kq + 3][row] = a.w;
        }
        // --- load B tile (BK x BN) ---
        #pragma unroll
        for (int r = 0; r < 2; r++) {
            int v = tid + r * NTHREADS;
            int krow = v >> 5;                   // 0..15
            int nq   = (v & 31) * 4;             // 0..124
            int kg   = kk + krow;
            float4 b;
            if (!jpath) {
                b = *(const float4*)(Wi1 + (size_t)kg * HIDDEN + (n0 + nq));
            } else {
                b = (kg < NDIM)
                    ? *(const float4*)(Wj1 + (size_t)kg * HIDDEN + (n0 - HIDDEN + nq))
                    : make_float4(0.f, 0.f, 0.f, 0.f);
            }
            *(float4*)&Bs[krow][nq] = b;
        }
        __syncthreads();

        // --- micro-kernel: 8x8 per thread, packed f32x2 ---
        #pragma unroll
        for (int k = 0; k < BK; k++) {
            float4 a0 = *(const float4*)&As[k][ty * TM];
            float4 a1 = *(const float4*)&As[k][ty * TM + 4];
            const unsigned long long* bp =
                (const unsigned long long*)&Bs[k][tx * TN];
            unsigned long long b0 = bp[0], b1 = bp[1], b2 = bp[2], b3 = bp[3];
            float av[8] = {a0.x, a0.y, a0.z, a0.w, a1.x, a1.y, a1.z, a1.w};
            #pragma unroll
            for (int i = 0; i < TM; i++) {
                unsigned long long ap = pack2(av[i], av[i]);
                acc[i][0] = ffma2(ap, b0, acc[i][0]);
                acc[i][1] = ffma2(ap, b1, acc[i][1]);
                acc[i][2] = ffma2(ap, b2, acc[i][2]);
                acc[i][3] = ffma2(ap, b3, acc[i][3]);
            }
        }
        __syncthreads();
    }

    // --- epilogue: bias + relu, store to Y ---
    const float* bias = jpath ? bj1 : bi1;
    const int nrel = jpath ? (n0 - HIDDEN) : n0;   // offset into the 512-wide bias
    const int nl = tx * TN;
    float bv[TN];
    #pragma unroll
    for (int j = 0; j < TN; j++) bv[j] = bias[nrel + nl + j];

    #pragma unroll
    for (int i = 0; i < TM; i++) {
        int m = m0 + ty * TM + i;
        if (m >= M_NODES) break;
        float o[TN];
        #pragma unroll
        for (int jp = 0; jp < TN / 2; jp++) unpack2(acc[i][jp], o[jp * 2], o[jp * 2 + 1]);
        float4 r0, r1;
        r0.x = fmaxf(o[0] + bv[0], 0.f);
        r0.y = fmaxf(o[1] + bv[1], 0.f);
        r0.z = fmaxf(o[2] + bv[2], 0.f);
        r0.w = fmaxf(o[3] + bv[3], 0.f);
        r1.x = fmaxf(o[4] + bv[4], 0.f);
        r1.y = fmaxf(o[5] + bv[5], 0.f);
        r1.z = fmaxf(o[6] + bv[6], 0.f);
        r1.w = fmaxf(o[7] + bv[7], 0.f);
        float* dst = g_Y + (size_t)m * N1 + n0 + nl;
        *(float4*)dst = r0;
        *(float4*)(dst + 4) = r1;
    }
}

// ---------- GEMM2: gate = sigmoid(Yi@Wi2+bi2); jv = Yj@Wj2+bj2; scatter-add gate*jv ----------
__global__ __launch_bounds__(NTHREADS)
void gemm2_kernel(const float* __restrict__ Wi2, const float* __restrict__ bi2,
                  const float* __restrict__ Wj2, const float* __restrict__ bj2,
                  const int* __restrict__ gidx, float* __restrict__ R) {
    __shared__ float As[BK][BM + 4];
    __shared__ float Bs[BK][BN + 4];
    __shared__ int sgi[BM];

    const int m0 = blockIdx.x * BM;
    const int tid = threadIdx.x;
    const int tx = tid & 15;
    const int ty = tid >> 4;

    if (tid < BM) {
        int m = m0 + tid;
        sgi[tid] = (m < M_NODES) ? gidx[m] : 0;
    }
    __syncthreads();

    float gate[TM][TN];

    // two passes: p=0 -> gate path (Y[:, :512] @ Wi2), p=1 -> value path (Y[:, 512:] @ Wj2)
    #pragma unroll 1
    for (int p = 0; p < 2; p++) {
        const float* W = (p == 0) ? Wi2 : Wj2;
        const int aoff = (p == 0) ? 0 : HIDDEN;

        unsigned long long acc[TM][TN / 2];
        #pragma unroll
        for (int i = 0; i < TM; i++)
            #pragma unroll
            for (int j = 0; j < TN / 2; j++) acc[i][j] = 0ull;

        for (int kk = 0; kk < HIDDEN; kk += BK) {
            #pragma unroll
            for (int r = 0; r < 2; r++) {
                int v = tid + r * NTHREADS;
                int row = v >> 2;
                int kq  = (v & 3) * 4;
                float4 a = make_float4(0.f, 0.f, 0.f, 0.f);
                int m = m0 + row;
                if (m < M_NODES)
                    a = *(const float4*)(g_Y + (size_t)m * N1 + aoff + kk + kq);
                As[kq + 0][row] = a.x;
                As[kq + 1][row] = a.y;
                As[kq + 2][row] = a.z;
                As[kq + 3][row] = a.w;
            }
            #pragma unroll
            for (int r = 0; r < 2; r++) {
                int v = tid + r * NTHREADS;
                int krow = v >> 5;
                int nq   = (v & 31) * 4;
                int kg   = kk + krow;
                *(float4*)&Bs[krow][nq] = *(const float4*)(W + (size_t)kg * GDIM + nq);
            }
            __syncthreads();

            #pragma unroll
            for (int k = 0; k < BK; k++) {
                float4 a0 = *(const float4*)&As[k][ty * TM];
                float4 a1 = *(const float4*)&As[k][ty * TM + 4];
                const unsigned long long* bp =
                    (const unsigned long long*)&Bs[k][tx * TN];
                unsigned long long b0 = bp[0], b1 = bp[1], b2 = bp[2], b3 = bp[3];
                float av[8] = {a0.x, a0.y, a0.z, a0.w, a1.x, a1.y, a1.z, a1.w};
                #pragma unroll
                for (int i = 0; i < TM; i++) {
                    unsigned long long ap = pack2(av[i], av[i]);
                    acc[i][0] = ffma2(ap, b0, acc[i][0]);
                    acc[i][1] = ffma2(ap, b1, acc[i][1]);
                    acc[i][2] = ffma2(ap, b2, acc[i][2]);
                    acc[i][3] = ffma2(ap, b3, acc[i][3]);
                }
            }
            __syncthreads();
        }

        // epilogue for this pass
        const float* bias = (p == 0) ? bi2 : bj2;
        const int nl = tx * TN;
        float bv[TN];
        #pragma unroll
        for (int j = 0; j < TN; j++) bv[j] = bias[nl + j];

        #pragma unroll
        for (int i = 0; i < TM; i++) {
            float o[TN];
            #pragma unroll
            for (int jp = 0; jp < TN / 2; jp++) unpack2(acc[i][jp], o[jp * 2], o[jp * 2 + 1]);
            #pragma unroll
            for (int j = 0; j < TN; j++) {
                float x = o[j] + bv[j];
                if (p == 0) {
                    gate[i][j] = 1.0f / (1.0f + expf(-x));   // sigmoid
                } else {
                    gate[i][j] *= x;                          // gate * jv = R_v
                }
            }
        }
    }

    // --- scatter-add into R[graph, n]; graph_index sorted -> run-length merge per thread ---
    const int rbase = ty * TM;
    #pragma unroll
    for (int j = 0; j < TN; j++) {
        int n = tx * TN + j;
        float sum = 0.f;
        int curg = -1;
        #pragma unroll
        for (int i = 0; i < TM; i++) {
            int m = m0 + rbase + i;
            if (m >= M_NODES) break;
            int g = sgi[rbase + i];
            float v = gate[i][j];
            if (g != curg) {
                if (curg >= 0) atomicAdd(&R[(size_t)curg * GDIM + n], sum);
                curg = g;
                sum = v;
            } else {
                sum += v;
            }
        }
        if (curg >= 0) atomicAdd(&R[(size_t)curg * GDIM + n], sum);
    }
}

// ---------- launch ----------
extern "C" void kernel_launch(void* const* d_in, const int* in_sizes, int n_in,
                              void* d_out, int out_size) {
    const float* h_T  = (const float*)d_in[0];
    const float* h_0  = (const float*)d_in[1];
    const int*   gidx = (const int*)d_in[2];
    const float* Wi1 = (const float*)d_in[3];
    const float* bi1 = (const float*)d_in[4];
    const float* Wi2 = (const float*)d_in[5];
    const float* bi2 = (const float*)d_in[6];
    const float* Wj1 = (const float*)d_in[7];
    const float* bj1 = (const float*)d_in[8];
    const float* Wj2 = (const float*)d_in[9];
    const float* bj2 = (const float*)d_in[10];
    float* R = (float*)d_out;

    zero_out_kernel<<<(NGRAPH * GDIM + 255) / 256, 256>>>(R, NGRAPH * GDIM);

    dim3 g1((M_NODES + BM - 1) / BM, N1 / BN);   // (1563, 8)
    gemm1_kernel<<<g1, NTHREADS>>>(h_T, h_0, Wi1, bi1, Wj1, bj1);

    gemm2_kernel<<<(M_NODES + BM - 1) / BM, NTHREADS>>>(Wi2, bi2, Wj2, bj2, gidx, R);
}

// round 6
// speedup vs baseline: 1.8257x; 1.8257x over previous
#include <cuda_runtime.h>
#include <cuda_bf16.h>
#include <cstdint>

#define M_NODES 200000
#define NGRAPH  1024
#define NT      256
#define BM      128
#define NTILES  ((M_NODES + BM - 1) / BM)

// ---- SMEM layout (bytes) ----
#define OFF_X    0           // 128 x 520 bf16 = 133120  (cols: 0-127 hT_hi,128-255 h0_hi,256-383 hT_lo,384-511 h0_lo)
#define X_PITCH  520
#define OFF_W1H  133120      // 64 x 136 bf16 = 17408
#define OFF_W1L  150528      // 17408
#define W1_PITCH 136
#define OFF_W2H  167936      // 128 x 72 bf16 = 18432
#define OFF_W2L  186368      // 18432
#define W2_PITCH 72
#define OFF_B1   204800      // 1024 f32
#define OFF_B2   208896      // 256 f32
#define OFF_GI   209920      // 128 int
#define SMEM_BYTES 210432
#define RV_PITCH 68          // fp32 scatter buffer aliased at OFF_W1H (128 x 68 x 4 = 34816 = W1H+W1L)

// ---- pre-split / pre-transposed weights  [n][k] row-major ----
__device__ __nv_bfloat16 g_w1i_hi[512 * 256];
__device__ __nv_bfloat16 g_w1i_lo[512 * 256];
__device__ __nv_bfloat16 g_w1j_hi[512 * 128];
__device__ __nv_bfloat16 g_w1j_lo[512 * 128];
__device__ __nv_bfloat16 g_w2i_hi[128 * 512];
__device__ __nv_bfloat16 g_w2i_lo[128 * 512];
__device__ __nv_bfloat16 g_w2j_hi[128 * 512];
__device__ __nv_bfloat16 g_w2j_lo[128 * 512];

__device__ __forceinline__ uint32_t smem_u32(const void* p) {
    uint32_t a;
    asm("{ .reg .u64 t; cvta.to.shared.u64 t, %1; cvt.u32.u64 %0, t; }" : "=r"(a) : "l"(p));
    return a;
}
__device__ __forceinline__ void ldm4(uint32_t r[4], uint32_t addr) {
    asm volatile("ldmatrix.sync.aligned.m8n8.x4.shared.b16 {%0,%1,%2,%3}, [%4];"
        : "=r"(r[0]), "=r"(r[1]), "=r"(r[2]), "=r"(r[3]) : "r"(addr));
}
__device__ __forceinline__ void mma16816(float d[4], const uint32_t a[4],
                                         uint32_t b0, uint32_t b1) {
    asm volatile("mma.sync.aligned.m16n8k16.row.col.f32.bf16.bf16.f32 "
        "{%0,%1,%2,%3}, {%4,%5,%6,%7}, {%8,%9}, {%0,%1,%2,%3};"
        : "+f"(d[0]), "+f"(d[1]), "+f"(d[2]), "+f"(d[3])
        : "r"(a[0]), "r"(a[1]), "r"(a[2]), "r"(a[3]), "r"(b0), "r"(b1));
}

// ---------- prep: split weights to bf16 hi/lo, transpose to [n][k] ----------
__global__ void prep_kernel(const float* __restrict__ Wi1, const float* __restrict__ Wj1,
                            const float* __restrict__ Wi2, const float* __restrict__ Wj2) {
    int idx = blockIdx.x * blockDim.x + threadIdx.x;
    float v; __nv_bfloat16 *dh, *dl; int pos;
    if (idx < 512 * 256) {
        int n = idx >> 8, k = idx & 255;
        v = Wi1[(size_t)k * 512 + n]; dh = g_w1i_hi; dl = g_w1i_lo; pos = idx;
    } else if (idx < 512 * 256 + 512 * 128) {
        int j = idx - 512 * 256; int n = j >> 7, k = j & 127;
        v = Wj1[(size_t)k * 512 + n]; dh = g_w1j_hi; dl = g_w1j_lo; pos = j;
    } else if (idx < 512 * 256 + 512 * 128 + 128 * 512) {
        int j = idx - 512 * 256 - 512 * 128; int n = j >> 9, k = j & 511;
        v = Wi2[(size_t)k * 128 + n]; dh = g_w2i_hi; dl = g_w2i_lo; pos = j;
    } else if (idx < 512 * 256 + 512 * 128 + 2 * 128 * 512) {
        int j = idx - 512 * 256 - 512 * 128 - 128 * 512; int n = j >> 9, k = j & 511;
        v = Wj2[(size_t)k * 128 + n]; dh = g_w2j_hi; dl = g_w2j_lo; pos = j;
    } else return;
    __nv_bfloat16 h = __float2bfloat16(v);
    dh[pos] = h;
    dl[pos] = __float2bfloat16(v - __bfloat162float(h));
}

__global__ void zero_out_kernel(float* __restrict__ R, int n) {
    int i = blockIdx.x * blockDim.x + threadIdx.x;
    if (i < n) R[i] = 0.0f;
}

// ---------- fused MLP + gate + segment-sum ----------
__global__ __launch_bounds__(NT, 1)
void fused_kernel(const float* __restrict__ hT, const float* __restrict__ h0,
                  const int* __restrict__ gidx,
                  const float* __restrict__ bi1, const float* __restrict__ bj1,
                  const float* __restrict__ bi2, const float* __restrict__ bj2,
                  float* __restrict__ R) {
    extern __shared__ char sm[];
    const uint32_t su = smem_u32(sm);
    const int tid = threadIdx.x;
    const int wid = tid >> 5, lane = tid & 31;
    const int m0 = blockIdx.x * BM;
    const int row0 = wid * 16;
    const int cq = lane & 3;          // l%4
    const int rql = lane >> 2;        // l/4

    float* b1s = (float*)(sm + OFF_B1);
    float* b2s = (float*)(sm + OFF_B2);
    int*   sgi = (int*)(sm + OFF_GI);

    // ---- stage bias / gidx ----
    for (int i = tid; i < 1024; i += NT) b1s[i] = (i < 512) ? bi1[i] : bj1[i - 512];
    for (int i = tid; i < 256;  i += NT) b2s[i] = (i < 128) ? bi2[i] : bj2[i - 128];
    if (tid < BM) { int m = m0 + tid; sgi[tid] = (m < M_NODES) ? gidx[m] : 0; }

    // ---- stage X = [hT|h0] hi/lo into SMEM ----
    {
        int m = m0 + (tid >> 1);
        int hf = tid & 1;                 // 64-element half
        bool valid = (m < M_NODES);
        __nv_bfloat162* xrow = (__nv_bfloat162*)(sm + OFF_X);
        #pragma unroll
        for (int src = 0; src < 2; src++) {
            const float* p = (src ? h0 : hT) + (size_t)m * 128 + hf * 64;
            int hib = src * 128 + hf * 64;
            int lob = 256 + hib;
            #pragma unroll
            for (int q = 0; q < 16; q++) {
                float4 v = valid ? ((const float4*)p)[q] : make_float4(0.f, 0.f, 0.f, 0.f);
                __nv_bfloat162 h0p = __floats2bfloat162_rn(v.x, v.y);
                __nv_bfloat162 h1p = __floats2bfloat162_rn(v.z, v.w);
                __nv_bfloat162 l0p = __floats2bfloat162_rn(v.x - __bfloat162float(h0p.x),
                                                           v.y - __bfloat162float(h0p.y));
                __nv_bfloat162 l1p = __floats2bfloat162_rn(v.z - __bfloat162float(h1p.x),
                                                           v.w - __bfloat162float(h1p.y));
                size_t base = (size_t)(tid >> 1) * (X_PITCH / 2);
                xrow[base + (hib >> 1) + 2 * q]     = h0p;
                xrow[base + (hib >> 1) + 2 * q + 1] = h1p;
                xrow[base + (lob >> 1) + 2 * q]     = l0p;
                xrow[base + (lob >> 1) + 2 * q + 1] = l1p;
            }
        }
    }
    __syncthreads();

    // ldmatrix lane address components
    const int arow = row0 + (lane & 15);
    const int acolo = (lane >> 4) << 3;                       // +0 / +8 in k
    const int bn = (lane & 7) + ((lane >> 4) << 3);           // n within n16 group
    const int bk = ((lane >> 3) & 1) << 3;                    // +0 / +8 in k
    const uint32_t xAaddr = su + (uint32_t)(arow * X_PITCH) * 2;  // + (col)*2 later
    const uint32_t w1hB = su + OFF_W1H + (uint32_t)(bn * W1_PITCH + bk) * 2;
    const uint32_t w1lB = su + OFF_W1L + (uint32_t)(bn * W1_PITCH + bk) * 2;
    const uint32_t w2hB = su + OFF_W2H + (uint32_t)(bn * W2_PITCH + bk) * 2;
    const uint32_t w2lB = su + OFF_W2L + (uint32_t)(bn * W2_PITCH + bk) * 2;

    float acc2[16][4];
    float gate[16][4];
    #pragma unroll
    for (int t = 0; t < 16; t++)
        #pragma unroll
        for (int q = 0; q < 4; q++) acc2[t][q] = 0.f;

    #pragma unroll 1
    for (int c = 0; c < 16; c++) {
        const bool ipath = (c < 8);
        const int c8 = c & 7;

        // ---- stage W2 chunk: [128 n][64 k] hi/lo ----
        {
            const __nv_bfloat16* sH = (ipath ? g_w2i_hi : g_w2j_hi) + c8 * 64;
            const __nv_bfloat16* sL = (ipath ? g_w2i_lo : g_w2j_lo) + c8 * 64;
            for (int i = tid; i < 1024; i += NT) {
                int r = i >> 3, q = i & 7;
                *(uint4*)(sm + OFF_W2H + r * (W2_PITCH * 2) + q * 16) =
                    *(const uint4*)(sH + (size_t)r * 512 + q * 8);
                *(uint4*)(sm + OFF_W2L + r * (W2_PITCH * 2) + q * 16) =
                    *(const uint4*)(sL + (size_t)r * 512 + q * 8);
            }
        }

        float acc1[8][4];
        #pragma unroll
        for (int t = 0; t < 8; t++)
            #pragma unroll
            for (int q = 0; q < 4; q++) acc1[t][q] = 0.f;

        const int nsl = ipath ? 2 : 1;
        #pragma unroll 1
        for (int s = 0; s < nsl; s++) {
            // ---- stage W1 slice: [64 n][128 k] hi/lo ----
            {
                const int kst = ipath ? 256 : 128;
                const __nv_bfloat16* sH = ipath ? (g_w1i_hi + (size_t)c * 64 * 256 + s * 128)
                                                : (g_w1j_hi + (size_t)c8 * 64 * 128);
                const __nv_bfloat16* sL = ipath ? (g_w1i_lo + (size_t)c * 64 * 256 + s * 128)
                                                : (g_w1j_lo + (size_t)c8 * 64 * 128);
                for (int i = tid; i < 1024; i += NT) {
                    int r = i >> 4, q = i & 15;
                    *(uint4*)(sm + OFF_W1H + r * (W1_PITCH * 2) + q * 16) =
                        *(const uint4*)(sH + (size_t)r * kst + q * 8);
                    *(uint4*)(sm + OFF_W1L + r * (W1_PITCH * 2) + q * 16) =
                        *(const uint4*)(sL + (size_t)r * kst + q * 8);
                }
            }
            __syncthreads();

            // ---- MMA1 over this K=128 slice (3 terms) ----
            #pragma unroll 2
            for (int k16 = 0; k16 < 8; k16++) {
                uint32_t ahi[4], alo[4];
                int colh = s * 128 + k16 * 16 + acolo;
                ldm4(ahi, xAaddr + (uint32_t)colh * 2);
                ldm4(alo, xAaddr + (uint32_t)(colh + 256) * 2);
                #pragma unroll
                for (int n16 = 0; n16 < 4; n16++) {
                    uint32_t bh[4], bl[4];
                    uint32_t koff = (uint32_t)(k16 * 16) * 2;
                    ldm4(bh, w1hB + (uint32_t)(n16 * 16 * W1_PITCH) * 2 + koff);
                    ldm4(bl, w1lB + (uint32_t)(n16 * 16 * W1_PITCH) * 2 + koff);
                    mma16816(acc1[2 * n16],     ahi, bh[0], bh[1]);
                    mma16816(acc1[2 * n16 + 1], ahi, bh[2], bh[3]);
                    mma16816(acc1[2 * n16],     alo, bh[0], bh[1]);
                    mma16816(acc1[2 * n16 + 1], alo, bh[2], bh[3]);
                    mma16816(acc1[2 * n16],     ahi, bl[0], bl[1]);
                    mma16816(acc1[2 * n16 + 1], ahi, bl[2], bl[3]);
                }
            }
            __syncthreads();   // W1 buffer reuse safety
        }

        // ---- epilogue: bias + ReLU + hi/lo split -> layer-2 A-frags (per-lane) ----
        uint32_t afh[4][4], afl[4][4];
        {
            const int bb = (ipath ? 0 : 512) + c8 * 64 + 2 * cq;
            #pragma unroll
            for (int t = 0; t < 8; t++) {
                float bz0 = b1s[bb + 8 * t], bz1 = b1s[bb + 8 * t + 1];
                float x0 = fmaxf(acc1[t][0] + bz0, 0.f);
                float x1 = fmaxf(acc1[t][1] + bz1, 0.f);
                float x2 = fmaxf(acc1[t][2] + bz0, 0.f);
                float x3 = fmaxf(acc1[t][3] + bz1, 0.f);
                __nv_bfloat162 h01 = __floats2bfloat162_rn(x0, x1);
                __nv_bfloat162 h23 = __floats2bfloat162_rn(x2, x3);
                __nv_bfloat162 l01 = __floats2bfloat162_rn(x0 - __bfloat162float(h01.x),
                                                           x1 - __bfloat162float(h01.y));
                __nv_bfloat162 l23 = __floats2bfloat162_rn(x2 - __bfloat162float(h23.x),
                                                           x3 - __bfloat162float(h23.y));
                int kb = t >> 1, off = (t & 1) * 2;
                afh[kb][off]     = *(uint32_t*)&h01;
                afh[kb][off + 1] = *(uint32_t*)&h23;
                afl[kb][off]     = *(uint32_t*)&l01;
                afl[kb][off + 1] = *(uint32_t*)&l23;
            }
        }

        // ---- MMA2: acc2 += Y @ W2chunk (3 terms) ----
        #pragma unroll
        for (int kb = 0; kb < 4; kb++) {
            #pragma unroll
            for (int n16 = 0; n16 < 8; n16++) {
                uint32_t bh[4], bl[4];
                uint32_t koff = (uint32_t)(kb * 16) * 2;
                ldm4(bh, w2hB + (uint32_t)(n16 * 16 * W2_PITCH) * 2 + koff);
                ldm4(bl, w2lB + (uint32_t)(n16 * 16 * W2_PITCH) * 2 + koff);
                mma16816(acc2[2 * n16],     afh[kb], bh[0], bh[1]);
                mma16816(acc2[2 * n16 + 1], afh[kb], bh[2], bh[3]);
                mma16816(acc2[2 * n16],     afl[kb], bh[0], bh[1]);
                mma16816(acc2[2 * n16 + 1], afl[kb], bh[2], bh[3]);
                mma16816(acc2[2 * n16],     afh[kb], bl[0], bl[1]);
                mma16816(acc2[2 * n16 + 1], afh[kb], bl[2], bl[3]);
            }
        }
        __syncthreads();   // protect W1/W2 buffers before next chunk's staging

        // ---- end of i-phase: gate = sigmoid(acc2 + bi2), reset acc2 ----
        if (c == 7) {
            #pragma unroll
            for (int t = 0; t < 16; t++) {
                int col = 8 * t + 2 * cq;
                float z0 = b2s[col], z1 = b2s[col + 1];
                gate[t][0] = 1.f / (1.f + __expf(-(acc2[t][0] + z0)));
                gate[t][1] = 1.f / (1.f + __expf(-(acc2[t][1] + z1)));
                gate[t][2] = 1.f / (1.f + __expf(-(acc2[t][2] + z0)));
                gate[t][3] = 1.f / (1.f + __expf(-(acc2[t][3] + z1)));
                acc2[t][0] = acc2[t][1] = acc2[t][2] = acc2[t][3] = 0.f;
            }
        }
    }

    // ---- Rv = gate * (jv + bj2) -> SMEM (two 64-col halves) -> merged scatter ----
    float* rvb = (float*)(sm + OFF_W1H);
    const int rA = row0 + rql, rB = rA + 8;
    #pragma unroll 1
    for (int hh = 0; hh < 2; hh++) {
        #pragma unroll
        for (int t = 0; t < 8; t++) {
            int tt = hh * 8 + t;
            int gcol = 8 * tt + 2 * cq;
            float z0 = b2s[128 + gcol], z1 = b2s[128 + gcol + 1];
            float v0 = gate[tt][0] * (acc2[tt][0] + z0);
            float v1 = gate[tt][1] * (acc2[tt][1] + z1);
            float v2 = gate[tt][2] * (acc2[tt][2] + z0);
            float v3 = gate[tt][3] * (acc2[tt][3] + z1);
            int lcol = 8 * t + 2 * cq;
            rvb[rA * RV_PITCH + lcol]     = v0;
            rvb[rA * RV_PITCH + lcol + 1] = v1;
            rvb[rB * RV_PITCH + lcol]     = v2;
            rvb[rB * RV_PITCH + lcol + 1] = v3;
        }
        __syncthreads();
        {
            int col = tid & 63, rg = tid >> 6;
            float sum = 0.f; int cur = -1;
            for (int r = rg * 32; r < rg * 32 + 32; r++) {
                int m = m0 + r;
                if (m >= M_NODES) break;
                int g = sgi[r];
                float v = rvb[r * RV_PITCH + col];
                if (g != cur) {
                    if (cur >= 0) atomicAdd(&R[(size_t)cur * 128 + hh * 64 + col], sum);
                    cur = g; sum = v;
                } else sum += v;
            }
            if (cur >= 0) atomicAdd(&R[(size_t)cur * 128 + hh * 64 + col], sum);
        }
        __syncthreads();
    }
}

// ---------------- launch ----------------
extern "C" void kernel_launch(void* const* d_in, const int* in_sizes, int n_in,
                              void* d_out, int out_size) {
    const float* h_T = (const float*)d_in[0];
    const float* h_0 = (const float*)d_in[1];
    const int*   gix = (const int*)d_in[2];
    const float* Wi1 = (const float*)d_in[3];
    const float* bi1 = (const float*)d_in[4];
    const float* Wi2 = (const float*)d_in[5];
    const float* bi2 = (const float*)d_in[6];
    const float* Wj1 = (const float*)d_in[7];
    const float* bj1 = (const float*)d_in[8];
    const float* Wj2 = (const float*)d_in[9];
    const float* bj2 = (const float*)d_in[10];
    float* R = (float*)d_out;

    cudaFuncSetAttribute(fused_kernel, cudaFuncAttributeMaxDynamicSharedMemorySize, SMEM_BYTES);

    int prep_elems = 512 * 256 + 512 * 128 + 2 * 128 * 512;
    prep_kernel<<<(prep_elems + 255) / 256, 256>>>(Wi1, Wj1, Wi2, Wj2);
    zero_out_kernel<<<(NGRAPH * 128 + 255) / 256, 256>>>(R, NGRAPH * 128);
    fused_kernel<<<NTILES, NT, SMEM_BYTES>>>(h_T, h_0, gix, bi1, bj1, bi2, bj2, R);
}

// round 7
// speedup vs baseline: 2.5528x; 1.3983x over previous
#include <cuda_runtime.h>
#include <cuda_fp16.h>
#include <cstdint>

#define M_NODES 200000
#define NGRAPH  1024
#define NT      256
#define BM      128
#define NTILES  ((M_NODES + BM - 1) / BM)

// ---- SMEM layout (bytes) ----
#define OFF_X     0          // 128 x 520 half = 133120 (cols 0-127 hT_hi,128-255 h0_hi,256-383 hT_lo,384-511 h0_lo)
#define X_PITCH   520
#define OFF_W1B0  133120     // 64 x 136 half = 17408 (double-buffered W1)
#define OFF_W1B1  150528
#define W1_PITCH  136
#define OFF_W2B0  167936     // 128 x 72 half = 18432 (double-buffered W2)
#define OFF_W2B1  186368
#define W2_PITCH  72
#define OFF_B1    204800     // 1024 f32
#define OFF_B2    208896     // 256 f32
#define OFF_GI    209920     // 128 int
#define SMEM_BYTES 210432
#define RV_PITCH  68         // fp32 scatter buffer aliased at OFF_W1B0 (128*68*4 = 34816 = both W1 bufs)

// ---- pre-rounded fp16 weights, [n][k] row-major ----
__device__ __half g_w1i[512 * 256];
__device__ __half g_w1j[512 * 128];
__device__ __half g_w2i[128 * 512];
__device__ __half g_w2j[128 * 512];

__device__ __forceinline__ uint32_t smem_u32(const void* p) {
    uint32_t a;
    asm("{ .reg .u64 t; cvta.to.shared.u64 t, %1; cvt.u32.u64 %0, t; }" : "=r"(a) : "l"(p));
    return a;
}
__device__ __forceinline__ void ldm4(uint32_t r[4], uint32_t addr) {
    asm volatile("ldmatrix.sync.aligned.m8n8.x4.shared.b16 {%0,%1,%2,%3}, [%4];"
        : "=r"(r[0]), "=r"(r[1]), "=r"(r[2]), "=r"(r[3]) : "r"(addr));
}
__device__ __forceinline__ void mma16816(float d[4], const uint32_t a[4],
                                         uint32_t b0, uint32_t b1) {
    asm volatile("mma.sync.aligned.m16n8k16.row.col.f32.f16.f16.f32 "
        "{%0,%1,%2,%3}, {%4,%5,%6,%7}, {%8,%9}, {%0,%1,%2,%3};"
        : "+f"(d[0]), "+f"(d[1]), "+f"(d[2]), "+f"(d[3])
        : "r"(a[0]), "r"(a[1]), "r"(a[2]), "r"(a[3]), "r"(b0), "r"(b1));
}
__device__ __forceinline__ void cpasync16(uint32_t dst, const void* src) {
    asm volatile("cp.async.cg.shared.global [%0], [%1], 16;" :: "r"(dst), "l"(src) : "memory");
}

// ---------- prep: round weights to fp16, transpose to [n][k] ----------
__global__ void prep_kernel(const float* __restrict__ Wi1, const float* __restrict__ Wj1,
                            const float* __restrict__ Wi2, const float* __restrict__ Wj2) {
    int idx = blockIdx.x * blockDim.x + threadIdx.x;
    if (idx < 512 * 256) {
        int n = idx >> 8, k = idx & 255;
        g_w1i[idx] = __float2half(Wi1[(size_t)k * 512 + n]);
    } else if (idx < 512 * 256 + 512 * 128) {
        int j = idx - 512 * 256; int n = j >> 7, k = j & 127;
        g_w1j[j] = __float2half(Wj1[(size_t)k * 512 + n]);
    } else if (idx < 512 * 256 + 512 * 128 + 128 * 512) {
        int j = idx - 512 * 256 - 512 * 128; int n = j >> 9, k = j & 511;
        g_w2i[j] = __float2half(Wi2[(size_t)k * 128 + n]);
    } else if (idx < 512 * 256 + 512 * 128 + 2 * 128 * 512) {
        int j = idx - 512 * 256 - 512 * 128 - 128 * 512; int n = j >> 9, k = j & 511;
        g_w2j[j] = __float2half(Wj2[(size_t)k * 128 + n]);
    }
}

__global__ void zero_out_kernel(float* __restrict__ R, int n) {
    int i = blockIdx.x * blockDim.x + threadIdx.x;
    if (i < n) R[i] = 0.0f;
}

// stage unit u (0..23): W1 slice (+W2 on first slice of a chunk) via cp.async; always commit.
// u<16: chunk c=u>>1 (i-path), slice s=u&1.  u>=16: chunk c=u-8 (j-path), s=0.
__device__ __forceinline__ void issue_stage(int u, uint32_t su, int tid) {
    if (u < 24) {
        int c, s;
        if (u < 16) { c = u >> 1; s = u & 1; } else { c = u - 8; s = 0; }
        const bool ipath = (c < 8);
        const int kst = ipath ? 256 : 128;
        const __half* src1 = ipath ? (g_w1i + (size_t)c * 64 * 256 + s * 128)
                                   : (g_w1j + (size_t)(c - 8) * 64 * 128);
        uint32_t dst1 = su + ((u & 1) ? OFF_W1B1 : OFF_W1B0);
        #pragma unroll
        for (int j = 0; j < 4; j++) {
            int idx = tid + j * 256;
            int r = idx >> 4, q = idx & 15;
            cpasync16(dst1 + (uint32_t)(r * (W1_PITCH * 2) + q * 16),
                      src1 + (size_t)r * kst + q * 8);
        }
        if (s == 0) {
            const __half* src2 = (ipath ? g_w2i : g_w2j) + (c & 7) * 64;
            uint32_t dst2 = su + ((c & 1) ? OFF_W2B1 : OFF_W2B0);
            #pragma unroll
            for (int j = 0; j < 4; j++) {
                int idx = tid + j * 256;
                int r = idx >> 3, q = idx & 7;
                cpasync16(dst2 + (uint32_t)(r * (W2_PITCH * 2) + q * 16),
                          src2 + (size_t)r * 512 + q * 8);
            }
        }
    }
    asm volatile("cp.async.commit_group;" ::: "memory");
}

// ---------- fused MLP + gate + segment-sum ----------
__global__ __launch_bounds__(NT, 1)
void fused_kernel(const float* __restrict__ hT, const float* __restrict__ h0,
                  const int* __restrict__ gidx,
                  const float* __restrict__ bi1, const float* __restrict__ bj1,
                  const float* __restrict__ bi2, const float* __restrict__ bj2,
                  float* __restrict__ R) {
    extern __shared__ char sm[];
    const uint32_t su = smem_u32(sm);
    const int tid = threadIdx.x;
    const int wid = tid >> 5, lane = tid & 31;
    const int m0 = blockIdx.x * BM;
    const int row0 = wid * 16;
    const int cq = lane & 3;
    const int rql = lane >> 2;

    float* b1s = (float*)(sm + OFF_B1);
    float* b2s = (float*)(sm + OFF_B2);
    int*   sgi = (int*)(sm + OFF_GI);

    // ---- stage bias / gidx ----
    for (int i = tid; i < 1024; i += NT) b1s[i] = (i < 512) ? bi1[i] : bj1[i - 512];
    for (int i = tid; i < 256;  i += NT) b2s[i] = (i < 128) ? bi2[i] : bj2[i - 128];
    if (tid < BM) { int m = m0 + tid; sgi[tid] = (m < M_NODES) ? gidx[m] : 0; }

    // ---- stage X = [hT|h0] fp16 hi/lo into SMEM ----
    {
        int m = m0 + (tid >> 1);
        int hf = tid & 1;
        bool valid = (m < M_NODES);
        __half2* xrow = (__half2*)(sm + OFF_X);
        #pragma unroll
        for (int src = 0; src < 2; src++) {
            const float* p = (src ? h0 : hT) + (size_t)m * 128 + hf * 64;
            int hib = src * 128 + hf * 64;
            int lob = 256 + hib;
            #pragma unroll
            for (int q = 0; q < 16; q++) {
                float4 v = valid ? ((const float4*)p)[q] : make_float4(0.f, 0.f, 0.f, 0.f);
                __half2 h0p = __floats2half2_rn(v.x, v.y);
                __half2 h1p = __floats2half2_rn(v.z, v.w);
                __half2 l0p = __floats2half2_rn(v.x - __half2float(__low2half(h0p)),
                                                v.y - __half2float(__high2half(h0p)));
                __half2 l1p = __floats2half2_rn(v.z - __half2float(__low2half(h1p)),
                                                v.w - __half2float(__high2half(h1p)));
                size_t base = (size_t)(tid >> 1) * (X_PITCH / 2);
                xrow[base + (hib >> 1) + 2 * q]     = h0p;
                xrow[base + (hib >> 1) + 2 * q + 1] = h1p;
                xrow[base + (lob >> 1) + 2 * q]     = l0p;
                xrow[base + (lob >> 1) + 2 * q + 1] = l1p;
            }
        }
    }

    // kick off first weight stage (group 0) — independent of X staging region
    issue_stage(0, su, tid);

    // ldmatrix lane address components
    const int arow = row0 + (lane & 15);
    const int acolo = (lane >> 4) << 3;
    const int bn = (lane & 7) + ((lane >> 4) << 3);
    const int bk = ((lane >> 3) & 1) << 3;
    const uint32_t xAaddr = su + (uint32_t)(arow * X_PITCH) * 2;
    const uint32_t w1B0 = su + OFF_W1B0 + (uint32_t)(bn * W1_PITCH + bk) * 2;
    const uint32_t w1B1 = su + OFF_W1B1 + (uint32_t)(bn * W1_PITCH + bk) * 2;
    const uint32_t w2B0 = su + OFF_W2B0 + (uint32_t)(bn * W2_PITCH + bk) * 2;
    const uint32_t w2B1 = su + OFF_W2B1 + (uint32_t)(bn * W2_PITCH + bk) * 2;

    float acc2[16][4];
    float gate[16][4];
    #pragma unroll
    for (int t = 0; t < 16; t++)
        #pragma unroll
        for (int q = 0; q < 4; q++) acc2[t][q] = 0.f;

    int u = 0;
    #pragma unroll 1
    for (int c = 0; c < 16; c++) {
        const bool ipath = (c < 8);
        const int c8 = c & 7;

        float acc1[8][4];
        #pragma unroll
        for (int t = 0; t < 8; t++)
            #pragma unroll
            for (int q = 0; q < 4; q++) acc1[t][q] = 0.f;

        const int nsl = ipath ? 2 : 1;
        #pragma unroll 1
        for (int s = 0; s < nsl; s++, u++) {
            __syncthreads();                       // prior MMA reads of target bufs complete
            issue_stage(u + 1, su, tid);           // stream next unit while we compute
            asm volatile("cp.async.wait_group 1;" ::: "memory");  // unit u landed
            __syncthreads();                       // visible to all warps

            const uint32_t wB = (u & 1) ? w1B1 : w1B0;
            #pragma unroll 2
            for (int k16 = 0; k16 < 8; k16++) {
                uint32_t ahi[4], alo[4];
                int colh = s * 128 + k16 * 16 + acolo;
                ldm4(ahi, xAaddr + (uint32_t)colh * 2);
                ldm4(alo, xAaddr + (uint32_t)(colh + 256) * 2);
                #pragma unroll
                for (int n16 = 0; n16 < 4; n16++) {
                    uint32_t bh[4];
                    ldm4(bh, wB + (uint32_t)(n16 * 16 * W1_PITCH + k16 * 16) * 2);
                    mma16816(acc1[2 * n16],     ahi, bh[0], bh[1]);
                    mma16816(acc1[2 * n16 + 1], ahi, bh[2], bh[3]);
                    mma16816(acc1[2 * n16],     alo, bh[0], bh[1]);
                    mma16816(acc1[2 * n16 + 1], alo, bh[2], bh[3]);
                }
            }
        }

        // ---- epilogue: bias + ReLU + fp16 hi/lo split -> layer-2 A-frags ----
        uint32_t afh[4][4], afl[4][4];
        {
            const int bb = (ipath ? 0 : 512) + c8 * 64 + 2 * cq;
            #pragma unroll
            for (int t = 0; t < 8; t++) {
                float bz0 = b1s[bb + 8 * t], bz1 = b1s[bb + 8 * t + 1];
                float x0 = fmaxf(acc1[t][0] + bz0, 0.f);
                float x1 = fmaxf(acc1[t][1] + bz1, 0.f);
                float x2 = fmaxf(acc1[t][2] + bz0, 0.f);
                float x3 = fmaxf(acc1[t][3] + bz1, 0.f);
                __half2 h01 = __floats2half2_rn(x0, x1);
                __half2 h23 = __floats2half2_rn(x2, x3);
                __half2 l01 = __floats2half2_rn(x0 - __half2float(__low2half(h01)),
                                                x1 - __half2float(__high2half(h01)));
                __half2 l23 = __floats2half2_rn(x2 - __half2float(__low2half(h23)),
                                                x3 - __half2float(__high2half(h23)));
                int kb = t >> 1, off = (t & 1) * 2;
                afh[kb][off]     = *(uint32_t*)&h01;
                afh[kb][off + 1] = *(uint32_t*)&h23;
                afl[kb][off]     = *(uint32_t*)&l01;
                afl[kb][off + 1] = *(uint32_t*)&l23;
            }
        }

        // ---- MMA2: acc2 += Y @ W2chunk (2 terms) ----
        {
            const uint32_t w2B = (c & 1) ? w2B1 : w2B0;
            #pragma unroll
            for (int kb = 0; kb < 4; kb++) {
                #pragma unroll
                for (int n16 = 0; n16 < 8; n16++) {
                    uint32_t bh[4];
                    ldm4(bh, w2B + (uint32_t)(n16 * 16 * W2_PITCH + kb * 16) * 2);
                    mma16816(acc2[2 * n16],     afh[kb], bh[0], bh[1]);
                    mma16816(acc2[2 * n16 + 1], afh[kb], bh[2], bh[3]);
                    mma16816(acc2[2 * n16],     afl[kb], bh[0], bh[1]);
                    mma16816(acc2[2 * n16 + 1], afl[kb], bh[2], bh[3]);
                }
            }
        }

        // ---- end of i-phase: gate = sigmoid(acc2 + bi2), reset acc2 ----
        if (c == 7) {
            #pragma unroll
            for (int t = 0; t < 16; t++) {
                int col = 8 * t + 2 * cq;
                float z0 = b2s[col], z1 = b2s[col + 1];
                gate[t][0] = 1.f / (1.f + __expf(-(acc2[t][0] + z0)));
                gate[t][1] = 1.f / (1.f + __expf(-(acc2[t][1] + z1)));
                gate[t][2] = 1.f / (1.f + __expf(-(acc2[t][2] + z0)));
                gate[t][3] = 1.f / (1.f + __expf(-(acc2[t][3] + z1)));
                acc2[t][0] = acc2[t][1] = acc2[t][2] = acc2[t][3] = 0.f;
            }
        }
    }

    __syncthreads();   // all MMA reads of W1 bufs done before aliasing as scatter buffer

    // ---- Rv = gate * (jv + bj2) -> SMEM (two 64-col halves) -> merged scatter ----
    float* rvb = (float*)(sm + OFF_W1B0);
    const int rA = row0 + rql, rB = rA + 8;
    #pragma unroll 1
    for (int hh = 0; hh < 2; hh++) {
        #pragma unroll
        for (int t = 0; t < 8; t++) {
            int tt = hh * 8 + t;
            int gcol = 8 * tt + 2 * cq;
            float z0 = b2s[128 + gcol], z1 = b2s[128 + gcol + 1];
            float v0 = gate[tt][0] * (acc2[tt][0] + z0);
            float v1 = gate[tt][1] * (acc2[tt][1] + z1);
            float v2 = gate[tt][2] * (acc2[tt][2] + z0);
            float v3 = gate[tt][3] * (acc2[tt][3] + z1);
            int lcol = 8 * t + 2 * cq;
            rvb[rA * RV_PITCH + lcol]     = v0;
            rvb[rA * RV_PITCH + lcol + 1] = v1;
            rvb[rB * RV_PITCH + lcol]     = v2;
            rvb[rB * RV_PITCH + lcol + 1] = v3;
        }
        __syncthreads();
        {
            int col = tid & 63, rg = tid >> 6;
            float sum = 0.f; int cur = -1;
            for (int r = rg * 32; r < rg * 32 + 32; r++) {
                int m = m0 + r;
                if (m >= M_NODES) break;
                int g = sgi[r];
                float v = rvb[r * RV_PITCH + col];
                if (g != cur) {
                    if (cur >= 0) atomicAdd(&R[(size_t)cur * 128 + hh * 64 + col], sum);
                    cur = g; sum = v;
                } else sum += v;
            }
            if (cur >= 0) atomicAdd(&R[(size_t)cur * 128 + hh * 64 + col], sum);
        }
        __syncthreads();
    }
}

// ---------------- launch ----------------
extern "C" void kernel_launch(void* const* d_in, const int* in_sizes, int n_in,
                              void* d_out, int out_size) {
    const float* h_T = (const float*)d_in[0];
    const float* h_0 = (const float*)d_in[1];
    const int*   gix = (const int*)d_in[2];
    const float* Wi1 = (const float*)d_in[3];
    const float* bi1 = (const float*)d_in[4];
    const float* Wi2 = (const float*)d_in[5];
    const float* bi2 = (const float*)d_in[6];
    const float* Wj1 = (const float*)d_in[7];
    const float* bj1 = (const float*)d_in[8];
    const float* Wj2 = (const float*)d_in[9];
    const float* bj2 = (const float*)d_in[10];
    float* R = (float*)d_out;

    cudaFuncSetAttribute(fused_kernel, cudaFuncAttributeMaxDynamicSharedMemorySize, SMEM_BYTES);

    int prep_elems = 512 * 256 + 512 * 128 + 2 * 128 * 512;
    prep_kernel<<<(prep_elems + 255) / 256, 256>>>(Wi1, Wj1, Wi2, Wj2);
    zero_out_kernel<<<(NGRAPH * 128 + 255) / 256, 256>>>(R, NGRAPH * 128);
    fused_kernel<<<NTILES, NT, SMEM_BYTES>>>(h_T, h_0, gix, bi1, bj1, bi2, bj2, R);
}

// round 8
// speedup vs baseline: 4.7685x; 1.8679x over previous
#include <cuda_runtime.h>
#include <cuda_fp16.h>
#include <cstdint>

#define M_NODES 200000
#define NGRAPH  1024
#define NT      256
#define BM      128
#define NTILES  ((M_NODES + BM - 1) / BM)

// ---- SMEM layout (bytes) ----
#define OFF_X     0          // 128 x 264 half = 67584 (cols 0-127 hT, 128-255 h0, fp16)
#define X_PITCH   264
#define OFF_W1B0  67584      // 64 x 136 half = 17408 (double-buffered W1)
#define OFF_W1B1  84992
#define W1_PITCH  136
#define OFF_W2B0  102400     // 128 x 72 half = 18432 (double-buffered W2)
#define OFF_W2B1  120832
#define W2_PITCH  72
#define OFF_B1    139264     // 1024 f32
#define OFF_B2    143360     // 256 f32
#define OFF_GI    144384     // 128 int
#define SMEM_BYTES 144896
#define RV_PITCH  68         // fp32 scatter buffer aliased at OFF_W1B0 (128*68*4 = 34816 = both W1 bufs)

// ---- pre-rounded fp16 weights, [n][k] row-major ----
__device__ __half g_w1i[512 * 256];
__device__ __half g_w1j[512 * 128];
__device__ __half g_w2i[128 * 512];
__device__ __half g_w2j[128 * 512];

__device__ __forceinline__ uint32_t smem_u32(const void* p) {
    uint32_t a;
    asm("{ .reg .u64 t; cvta.to.shared.u64 t, %1; cvt.u32.u64 %0, t; }" : "=r"(a) : "l"(p));
    return a;
}
__device__ __forceinline__ void ldm4(uint32_t r[4], uint32_t addr) {
    asm volatile("ldmatrix.sync.aligned.m8n8.x4.shared.b16 {%0,%1,%2,%3}, [%4];"
        : "=r"(r[0]), "=r"(r[1]), "=r"(r[2]), "=r"(r[3]) : "r"(addr));
}
__device__ __forceinline__ void mma16816(float d[4], const uint32_t a[4],
                                         uint32_t b0, uint32_t b1) {
    asm volatile("mma.sync.aligned.m16n8k16.row.col.f32.f16.f16.f32 "
        "{%0,%1,%2,%3}, {%4,%5,%6,%7}, {%8,%9}, {%0,%1,%2,%3};"
        : "+f"(d[0]), "+f"(d[1]), "+f"(d[2]), "+f"(d[3])
        : "r"(a[0]), "r"(a[1]), "r"(a[2]), "r"(a[3]), "r"(b0), "r"(b1));
}
__device__ __forceinline__ void cpasync16(uint32_t dst, const void* src) {
    asm volatile("cp.async.cg.shared.global [%0], [%1], 16;" :: "r"(dst), "l"(src) : "memory");
}

// ---------- prep: round weights to fp16, transpose to [n][k] ----------
__global__ void prep_kernel(const float* __restrict__ Wi1, const float* __restrict__ Wj1,
                            const float* __restrict__ Wi2, const float* __restrict__ Wj2) {
    int idx = blockIdx.x * blockDim.x + threadIdx.x;
    if (idx < 512 * 256) {
        int n = idx >> 8, k = idx & 255;
        g_w1i[idx] = __float2half(Wi1[(size_t)k * 512 + n]);
    } else if (idx < 512 * 256 + 512 * 128) {
        int j = idx - 512 * 256; int n = j >> 7, k = j & 127;
        g_w1j[j] = __float2half(Wj1[(size_t)k * 512 + n]);
    } else if (idx < 512 * 256 + 512 * 128 + 128 * 512) {
        int j = idx - 512 * 256 - 512 * 128; int n = j >> 9, k = j & 511;
        g_w2i[j] = __float2half(Wi2[(size_t)k * 128 + n]);
    } else if (idx < 512 * 256 + 512 * 128 + 2 * 128 * 512) {
        int j = idx - 512 * 256 - 512 * 128 - 128 * 512; int n = j >> 9, k = j & 511;
        g_w2j[j] = __float2half(Wj2[(size_t)k * 128 + n]);
    }
}

__global__ void zero_out_kernel(float* __restrict__ R, int n) {
    int i = blockIdx.x * blockDim.x + threadIdx.x;
    if (i < n) R[i] = 0.0f;
}

// stage unit u (0..23): W1 slice (+W2 on first slice of a chunk) via cp.async; always commit.
// u<16: chunk c=u>>1 (i-path), slice s=u&1.  u>=16: chunk c=u-8 (j-path), s=0.
__device__ __forceinline__ void issue_stage(int u, uint32_t su, int tid) {
    if (u < 24) {
        int c, s;
        if (u < 16) { c = u >> 1; s = u & 1; } else { c = u - 8; s = 0; }
        const bool ipath = (c < 8);
        const int kst = ipath ? 256 : 128;
        const __half* src1 = ipath ? (g_w1i + (size_t)c * 64 * 256 + s * 128)
                                   : (g_w1j + (size_t)(c - 8) * 64 * 128);
        uint32_t dst1 = su + ((u & 1) ? OFF_W1B1 : OFF_W1B0);
        #pragma unroll
        for (int j = 0; j < 4; j++) {
            int idx = tid + j * 256;
            int r = idx >> 4, q = idx & 15;
            cpasync16(dst1 + (uint32_t)(r * (W1_PITCH * 2) + q * 16),
                      src1 + (size_t)r * kst + q * 8);
        }
        if (s == 0) {
            const __half* src2 = (ipath ? g_w2i : g_w2j) + (c & 7) * 64;
            uint32_t dst2 = su + ((c & 1) ? OFF_W2B1 : OFF_W2B0);
            #pragma unroll
            for (int j = 0; j < 4; j++) {
                int idx = tid + j * 256;
                int r = idx >> 3, q = idx & 7;
                cpasync16(dst2 + (uint32_t)(r * (W2_PITCH * 2) + q * 16),
                          src2 + (size_t)r * 512 + q * 8);
            }
        }
    }
    asm volatile("cp.async.commit_group;" ::: "memory");
}

// ---------- fused MLP + gate + segment-sum ----------
__global__ __launch_bounds__(NT, 1)
void fused_kernel(const float* __restrict__ hT, const float* __restrict__ h0,
                  const int* __restrict__ gidx,
                  const float* __restrict__ bi1, const float* __restrict__ bj1,
                  const float* __restrict__ bi2, const float* __restrict__ bj2,
                  float* __restrict__ R) {
    extern __shared__ char sm[];
    const uint32_t su = smem_u32(sm);
    const int tid = threadIdx.x;
    const int wid = tid >> 5, lane = tid & 31;
    const int m0 = blockIdx.x * BM;
    const int row0 = wid * 16;
    const int cq = lane & 3;
    const int rql = lane >> 2;

    float* b1s = (float*)(sm + OFF_B1);
    float* b2s = (float*)(sm + OFF_B2);
    int*   sgi = (int*)(sm + OFF_GI);

    // ---- stage bias / gidx ----
    for (int i = tid; i < 1024; i += NT) b1s[i] = (i < 512) ? bi1[i] : bj1[i - 512];
    for (int i = tid; i < 256;  i += NT) b2s[i] = (i < 128) ? bi2[i] : bj2[i - 128];
    if (tid < BM) { int m = m0 + tid; sgi[tid] = (m < M_NODES) ? gidx[m] : 0; }

    // ---- stage X = [hT|h0] fp16 into SMEM ----
    {
        int m = m0 + (tid >> 1);
        int hf = tid & 1;
        bool valid = (m < M_NODES);
        __half2* xrow = (__half2*)(sm + OFF_X);
        #pragma unroll
        for (int src = 0; src < 2; src++) {
            const float* p = (src ? h0 : hT) + (size_t)m * 128 + hf * 64;
            int hib = src * 128 + hf * 64;
            #pragma unroll
            for (int q = 0; q < 16; q++) {
                float4 v = valid ? ((const float4*)p)[q] : make_float4(0.f, 0.f, 0.f, 0.f);
                __half2 h0p = __floats2half2_rn(v.x, v.y);
                __half2 h1p = __floats2half2_rn(v.z, v.w);
                size_t base = (size_t)(tid >> 1) * (X_PITCH / 2);
                xrow[base + (hib >> 1) + 2 * q]     = h0p;
                xrow[base + (hib >> 1) + 2 * q + 1] = h1p;
            }
        }
    }

    // kick off first weight stage (group 0) — independent of X staging region
    issue_stage(0, su, tid);

    // ldmatrix lane address components
    const int arow = row0 + (lane & 15);
    const int acolo = (lane >> 4) << 3;
    const int bn = (lane & 7) + ((lane >> 4) << 3);
    const int bk = ((lane >> 3) & 1) << 3;
    const uint32_t xAaddr = su + (uint32_t)(arow * X_PITCH) * 2;
    const uint32_t w1B0 = su + OFF_W1B0 + (uint32_t)(bn * W1_PITCH + bk) * 2;
    const uint32_t w1B1 = su + OFF_W1B1 + (uint32_t)(bn * W1_PITCH + bk) * 2;
    const uint32_t w2B0 = su + OFF_W2B0 + (uint32_t)(bn * W2_PITCH + bk) * 2;
    const uint32_t w2B1 = su + OFF_W2B1 + (uint32_t)(bn * W2_PITCH + bk) * 2;

    float acc2[16][4];
    float gate[16][4];
    #pragma unroll
    for (int t = 0; t < 16; t++)
        #pragma unroll
        for (int q = 0; q < 4; q++) acc2[t][q] = 0.f;

    int u = 0;
    #pragma unroll 1
    for (int c = 0; c < 16; c++) {
        const bool ipath = (c < 8);
        const int c8 = c & 7;

        float acc1[8][4];
        #pragma unroll
        for (int t = 0; t < 8; t++)
            #pragma unroll
            for (int q = 0; q < 4; q++) acc1[t][q] = 0.f;

        const int nsl = ipath ? 2 : 1;
        #pragma unroll 1
        for (int s = 0; s < nsl; s++, u++) {
            __syncthreads();                       // prior MMA reads of target bufs complete
            issue_stage(u + 1, su, tid);           // stream next unit while we compute
            asm volatile("cp.async.wait_group 1;" ::: "memory");  // unit u landed
            __syncthreads();                       // visible to all warps

            const uint32_t wB = (u & 1) ? w1B1 : w1B0;
            #pragma unroll 2
            for (int k16 = 0; k16 < 8; k16++) {
                uint32_t ahi[4];
                int colh = s * 128 + k16 * 16 + acolo;
                ldm4(ahi, xAaddr + (uint32_t)colh * 2);
                #pragma unroll
                for (int n16 = 0; n16 < 4; n16++) {
                    uint32_t bh[4];
                    ldm4(bh, wB + (uint32_t)(n16 * 16 * W1_PITCH + k16 * 16) * 2);
                    mma16816(acc1[2 * n16],     ahi, bh[0], bh[1]);
                    mma16816(acc1[2 * n16 + 1], ahi, bh[2], bh[3]);
                }
            }
        }

        // ---- epilogue: bias + ReLU + fp16 round -> layer-2 A-frags ----
        uint32_t afh[4][4];
        {
            const int bb = (ipath ? 0 : 512) + c8 * 64 + 2 * cq;
            #pragma unroll
            for (int t = 0; t < 8; t++) {
                float bz0 = b1s[bb + 8 * t], bz1 = b1s[bb + 8 * t + 1];
                float x0 = fmaxf(acc1[t][0] + bz0, 0.f);
                float x1 = fmaxf(acc1[t][1] + bz1, 0.f);
                float x2 = fmaxf(acc1[t][2] + bz0, 0.f);
                float x3 = fmaxf(acc1[t][3] + bz1, 0.f);
                __half2 h01 = __floats2half2_rn(x0, x1);
                __half2 h23 = __floats2half2_rn(x2, x3);
                int kb = t >> 1, off = (t & 1) * 2;
                afh[kb][off]     = *(uint32_t*)&h01;
                afh[kb][off + 1] = *(uint32_t*)&h23;
            }
        }

        // ---- MMA2: acc2 += Y @ W2chunk ----
        {
            const uint32_t w2B = (c & 1) ? w2B1 : w2B0;
            #pragma unroll
            for (int kb = 0; kb < 4; kb++) {
                #pragma unroll
                for (int n16 = 0; n16 < 8; n16++) {
                    uint32_t bh[4];
                    ldm4(bh, w2B + (uint32_t)(n16 * 16 * W2_PITCH + kb * 16) * 2);
                    mma16816(acc2[2 * n16],     afh[kb], bh[0], bh[1]);
                    mma16816(acc2[2 * n16 + 1], afh[kb], bh[2], bh[3]);
                }
            }
        }

        // ---- end of i-phase: gate = sigmoid(acc2 + bi2), reset acc2 ----
        if (c == 7) {
            #pragma unroll
            for (int t = 0; t < 16; t++) {
                int col = 8 * t + 2 * cq;
                float z0 = b2s[col], z1 = b2s[col + 1];
                gate[t][0] = 1.f / (1.f + __expf(-(acc2[t][0] + z0)));
                gate[t][1] = 1.f / (1.f + __expf(-(acc2[t][1] + z1)));
                gate[t][2] = 1.f / (1.f + __expf(-(acc2[t][2] + z0)));
                gate[t][3] = 1.f / (1.f + __expf(-(acc2[t][3] + z1)));
                acc2[t][0] = acc2[t][1] = acc2[t][2] = acc2[t][3] = 0.f;
            }
        }
    }

    __syncthreads();   // all MMA reads of W1 bufs done before aliasing as scatter buffer

    // ---- Rv = gate * (jv + bj2) -> SMEM (two 64-col halves) -> merged scatter ----
    float* rvb = (float*)(sm + OFF_W1B0);
    const int rA = row0 + rql, rB = rA + 8;
    #pragma unroll 1
    for (int hh = 0; hh < 2; hh++) {
        #pragma unroll
        for (int t = 0; t < 8; t++) {
            int tt = hh * 8 + t;
            int gcol = 8 * tt + 2 * cq;
            float z0 = b2s[128 + gcol], z1 = b2s[128 + gcol + 1];
            float v0 = gate[tt][0] * (acc2[tt][0] + z0);
            float v1 = gate[tt][1] * (acc2[tt][1] + z1);
            float v2 = gate[tt][2] * (acc2[tt][2] + z0);
            float v3 = gate[tt][3] * (acc2[tt][3] + z1);
            int lcol = 8 * t + 2 * cq;
            rvb[rA * RV_PITCH + lcol]     = v0;
            rvb[rA * RV_PITCH + lcol + 1] = v1;
            rvb[rB * RV_PITCH + lcol]     = v2;
            rvb[rB * RV_PITCH + lcol + 1] = v3;
        }
        __syncthreads();
        {
            int col = tid & 63, rg = tid >> 6;
            float sum = 0.f; int cur = -1;
            for (int r = rg * 32; r < rg * 32 + 32; r++) {
                int m = m0 + r;
                if (m >= M_NODES) break;
                int g = sgi[r];
                float v = rvb[r * RV_PITCH + col];
                if (g != cur) {
                    if (cur >= 0) atomicAdd(&R[(size_t)cur * 128 + hh * 64 + col], sum);
                    cur = g; sum = v;
                } else sum += v;
            }
            if (cur >= 0) atomicAdd(&R[(size_t)cur * 128 + hh * 64 + col], sum);
        }
        __syncthreads();
    }
}

// ---------------- launch ----------------
extern "C" void kernel_launch(void* const* d_in, const int* in_sizes, int n_in,
                              void* d_out, int out_size) {
    const float* h_T = (const float*)d_in[0];
    const float* h_0 = (const float*)d_in[1];
    const int*   gix = (const int*)d_in[2];
    const float* Wi1 = (const float*)d_in[3];
    const float* bi1 = (const float*)d_in[4];
    const float* Wi2 = (const float*)d_in[5];
    const float* bi2 = (const float*)d_in[6];
    const float* Wj1 = (const float*)d_in[7];
    const float* bj1 = (const float*)d_in[8];
    const float* Wj2 = (const float*)d_in[9];
    const float* bj2 = (const float*)d_in[10];
    float* R = (float*)d_out;

    cudaFuncSetAttribute(fused_kernel, cudaFuncAttributeMaxDynamicSharedMemorySize, SMEM_BYTES);

    int prep_elems = 512 * 256 + 512 * 128 + 2 * 128 * 512;
    prep_kernel<<<(prep_elems + 255) / 256, 256>>>(Wi1, Wj1, Wi2, Wj2);
    zero_out_kernel<<<(NGRAPH * 128 + 255) / 256, 256>>>(R, NGRAPH * 128);
    fused_kernel<<<NTILES, NT, SMEM_BYTES>>>(h_T, h_0, gix, bi1, bj1, bi2, bj2, R);
}

// round 9
// speedup vs baseline: 4.9341x; 1.0347x over previous
#include <cuda_runtime.h>
#include <cuda_fp16.h>
#include <cstdint>

#define M_NODES 200000
#define NGRAPH  1024
#define NT      128
#define BM      64
#define NTILES  ((M_NODES + BM - 1) / BM)   // 3125

// ---- SMEM layout (bytes) ----
#define OFF_X     0          // 64 x 264 half = 33792 (cols 0-127 hT, 128-255 h0, fp16)
#define X_PITCH   264
#define OFF_W1B0  33792      // 64 x 136 half = 17408 (double-buffered W1)
#define OFF_W1B1  51200
#define W1_PITCH  136
#define OFF_W2B0  68608      // 128 x 72 half = 18432 (double-buffered W2)
#define OFF_W2B1  87040
#define W2_PITCH  72
#define OFF_B1    105472     // 1024 f32
#define OFF_B2    109568     // 256 f32
#define OFF_GI    110592     // 64 int
#define SMEM_BYTES 110848
#define RV_PITCH  68         // fp32 scatter buffer aliased at OFF_W1B0 (64*68*4 = 17408 = one W1 buf)

// ---- pre-rounded fp16 weights, [n][k] row-major ----
__device__ __half g_w1i[512 * 256];
__device__ __half g_w1j[512 * 128];
__device__ __half g_w2i[128 * 512];
__device__ __half g_w2j[128 * 512];

__device__ __forceinline__ uint32_t smem_u32(const void* p) {
    uint32_t a;
    asm("{ .reg .u64 t; cvta.to.shared.u64 t, %1; cvt.u32.u64 %0, t; }" : "=r"(a) : "l"(p));
    return a;
}
__device__ __forceinline__ void ldm4(uint32_t r[4], uint32_t addr) {
    asm volatile("ldmatrix.sync.aligned.m8n8.x4.shared.b16 {%0,%1,%2,%3}, [%4];"
        : "=r"(r[0]), "=r"(r[1]), "=r"(r[2]), "=r"(r[3]) : "r"(addr));
}
__device__ __forceinline__ void mma16816(float d[4], const uint32_t a[4],
                                         uint32_t b0, uint32_t b1) {
    asm volatile("mma.sync.aligned.m16n8k16.row.col.f32.f16.f16.f32 "
        "{%0,%1,%2,%3}, {%4,%5,%6,%7}, {%8,%9}, {%0,%1,%2,%3};"
        : "+f"(d[0]), "+f"(d[1]), "+f"(d[2]), "+f"(d[3])
        : "r"(a[0]), "r"(a[1]), "r"(a[2]), "r"(a[3]), "r"(b0), "r"(b1));
}
__device__ __forceinline__ void cpasync16(uint32_t dst, const void* src) {
    asm volatile("cp.async.cg.shared.global [%0], [%1], 16;" :: "r"(dst), "l"(src) : "memory");
}

// ---------- prep: round weights to fp16, transpose to [n][k] ----------
__global__ void prep_kernel(const float* __restrict__ Wi1, const float* __restrict__ Wj1,
                            const float* __restrict__ Wi2, const float* __restrict__ Wj2) {
    int idx = blockIdx.x * blockDim.x + threadIdx.x;
    if (idx < 512 * 256) {
        int n = idx >> 8, k = idx & 255;
        g_w1i[idx] = __float2half(Wi1[(size_t)k * 512 + n]);
    } else if (idx < 512 * 256 + 512 * 128) {
        int j = idx - 512 * 256; int n = j >> 7, k = j & 127;
        g_w1j[j] = __float2half(Wj1[(size_t)k * 512 + n]);
    } else if (idx < 512 * 256 + 512 * 128 + 128 * 512) {
        int j = idx - 512 * 256 - 512 * 128; int n = j >> 9, k = j & 511;
        g_w2i[j] = __float2half(Wi2[(size_t)k * 128 + n]);
    } else if (idx < 512 * 256 + 512 * 128 + 2 * 128 * 512) {
        int j = idx - 512 * 256 - 512 * 128 - 128 * 512; int n = j >> 9, k = j & 511;
        g_w2j[j] = __float2half(Wj2[(size_t)k * 128 + n]);
    }
}

__global__ void zero_out_kernel(float* __restrict__ R, int n) {
    int i = blockIdx.x * blockDim.x + threadIdx.x;
    if (i < n) R[i] = 0.0f;
}

// stage unit u (0..23): W1 slice (+W2 on first slice of a chunk) via cp.async; always commit.
// u<16: chunk c=u>>1 (i-path), slice s=u&1.  u>=16: chunk c=u-8 (j-path), s=0.
__device__ __forceinline__ void issue_stage(int u, uint32_t su, int tid) {
    if (u < 24) {
        int c, s;
        if (u < 16) { c = u >> 1; s = u & 1; } else { c = u - 8; s = 0; }
        const bool ipath = (c < 8);
        const int kst = ipath ? 256 : 128;
        const __half* src1 = ipath ? (g_w1i + (size_t)c * 64 * 256 + s * 128)
                                   : (g_w1j + (size_t)(c - 8) * 64 * 128);
        uint32_t dst1 = su + ((u & 1) ? OFF_W1B1 : OFF_W1B0);
        #pragma unroll
        for (int j = 0; j < 8; j++) {
            int idx = tid + j * NT;
            int r = idx >> 4, q = idx & 15;
            cpasync16(dst1 + (uint32_t)(r * (W1_PITCH * 2) + q * 16),
                      src1 + (size_t)r * kst + q * 8);
        }
        if (s == 0) {
            const __half* src2 = (ipath ? g_w2i : g_w2j) + (c & 7) * 64;
            uint32_t dst2 = su + ((c & 1) ? OFF_W2B1 : OFF_W2B0);
            #pragma unroll
            for (int j = 0; j < 8; j++) {
                int idx = tid + j * NT;
                int r = idx >> 3, q = idx & 7;
                cpasync16(dst2 + (uint32_t)(r * (W2_PITCH * 2) + q * 16),
                          src2 + (size_t)r * 512 + q * 8);
            }
        }
    }
    asm volatile("cp.async.commit_group;" ::: "memory");
}

// ---------- fused MLP + gate + segment-sum ----------
__global__ __launch_bounds__(NT, 2)
void fused_kernel(const float* __restrict__ hT, const float* __restrict__ h0,
                  const int* __restrict__ gidx,
                  const float* __restrict__ bi1, const float* __restrict__ bj1,
                  const float* __restrict__ bi2, const float* __restrict__ bj2,
                  float* __restrict__ R) {
    extern __shared__ char sm[];
    const uint32_t su = smem_u32(sm);
    const int tid = threadIdx.x;
    const int wid = tid >> 5, lane = tid & 31;
    const int m0 = blockIdx.x * BM;
    const int row0 = wid * 16;
    const int cq = lane & 3;
    const int rql = lane >> 2;

    float* b1s = (float*)(sm + OFF_B1);
    float* b2s = (float*)(sm + OFF_B2);
    int*   sgi = (int*)(sm + OFF_GI);

    // ---- stage bias / gidx ----
    for (int i = tid; i < 1024; i += NT) b1s[i] = (i < 512) ? bi1[i] : bj1[i - 512];
    for (int i = tid; i < 256;  i += NT) b2s[i] = (i < 128) ? bi2[i] : bj2[i - 128];
    if (tid < BM) { int m = m0 + tid; sgi[tid] = (m < M_NODES) ? gidx[m] : 0; }

    // ---- stage X = [hT|h0] fp16 into SMEM (64 rows, 128 threads) ----
    {
        int m = m0 + (tid >> 1);
        int hf = tid & 1;
        bool valid = (m < M_NODES);
        __half2* xrow = (__half2*)(sm + OFF_X);
        #pragma unroll
        for (int src = 0; src < 2; src++) {
            const float* p = (src ? h0 : hT) + (size_t)m * 128 + hf * 64;
            int hib = src * 128 + hf * 64;
            #pragma unroll
            for (int q = 0; q < 16; q++) {
                float4 v = valid ? ((const float4*)p)[q] : make_float4(0.f, 0.f, 0.f, 0.f);
                __half2 h0p = __floats2half2_rn(v.x, v.y);
                __half2 h1p = __floats2half2_rn(v.z, v.w);
                size_t base = (size_t)(tid >> 1) * (X_PITCH / 2);
                xrow[base + (hib >> 1) + 2 * q]     = h0p;
                xrow[base + (hib >> 1) + 2 * q + 1] = h1p;
            }
        }
    }

    // kick off first weight stage (group 0) — independent of X staging region
    issue_stage(0, su, tid);

    // ldmatrix lane address components
    const int arow = row0 + (lane & 15);
    const int acolo = (lane >> 4) << 3;
    const int bn = (lane & 7) + ((lane >> 4) << 3);
    const int bk = ((lane >> 3) & 1) << 3;
    const uint32_t xAaddr = su + (uint32_t)(arow * X_PITCH) * 2;
    const uint32_t w1B0 = su + OFF_W1B0 + (uint32_t)(bn * W1_PITCH + bk) * 2;
    const uint32_t w1B1 = su + OFF_W1B1 + (uint32_t)(bn * W1_PITCH + bk) * 2;
    const uint32_t w2B0 = su + OFF_W2B0 + (uint32_t)(bn * W2_PITCH + bk) * 2;
    const uint32_t w2B1 = su + OFF_W2B1 + (uint32_t)(bn * W2_PITCH + bk) * 2;

    float acc2[16][4];
    float gate[16][4];
    #pragma unroll
    for (int t = 0; t < 16; t++)
        #pragma unroll
        for (int q = 0; q < 4; q++) acc2[t][q] = 0.f;

    int u = 0;
    #pragma unroll 1
    for (int c = 0; c < 16; c++) {
        const bool ipath = (c < 8);
        const int c8 = c & 7;

        float acc1[8][4];
        #pragma unroll
        for (int t = 0; t < 8; t++)
            #pragma unroll
            for (int q = 0; q < 4; q++) acc1[t][q] = 0.f;

        const int nsl = ipath ? 2 : 1;
        #pragma unroll 1
        for (int s = 0; s < nsl; s++, u++) {
            __syncthreads();                       // prior MMA reads of target bufs complete
            issue_stage(u + 1, su, tid);           // stream next unit while we compute
            asm volatile("cp.async.wait_group 1;" ::: "memory");  // unit u landed
            __syncthreads();                       // visible to all warps

            const uint32_t wB = (u & 1) ? w1B1 : w1B0;
            #pragma unroll 2
            for (int k16 = 0; k16 < 8; k16++) {
                uint32_t ahi[4];
                int colh = s * 128 + k16 * 16 + acolo;
                ldm4(ahi, xAaddr + (uint32_t)colh * 2);
                #pragma unroll
                for (int n16 = 0; n16 < 4; n16++) {
                    uint32_t bh[4];
                    ldm4(bh, wB + (uint32_t)(n16 * 16 * W1_PITCH + k16 * 16) * 2);
                    mma16816(acc1[2 * n16],     ahi, bh[0], bh[1]);
                    mma16816(acc1[2 * n16 + 1], ahi, bh[2], bh[3]);
                }
            }
        }

        // ---- epilogue: bias + ReLU + fp16 round -> layer-2 A-frags ----
        uint32_t afh[4][4];
        {
            const int bb = (ipath ? 0 : 512) + c8 * 64 + 2 * cq;
            #pragma unroll
            for (int t = 0; t < 8; t++) {
                float bz0 = b1s[bb + 8 * t], bz1 = b1s[bb + 8 * t + 1];
                float x0 = fmaxf(acc1[t][0] + bz0, 0.f);
                float x1 = fmaxf(acc1[t][1] + bz1, 0.f);
                float x2 = fmaxf(acc1[t][2] + bz0, 0.f);
                float x3 = fmaxf(acc1[t][3] + bz1, 0.f);
                __half2 h01 = __floats2half2_rn(x0, x1);
                __half2 h23 = __floats2half2_rn(x2, x3);
                int kb = t >> 1, off = (t & 1) * 2;
                afh[kb][off]     = *(uint32_t*)&h01;
                afh[kb][off + 1] = *(uint32_t*)&h23;
            }
        }

        // ---- MMA2: acc2 += Y @ W2chunk ----
        {
            const uint32_t w2B = (c & 1) ? w2B1 : w2B0;
            #pragma unroll
            for (int kb = 0; kb < 4; kb++) {
                #pragma unroll
                for (int n16 = 0; n16 < 8; n16++) {
                    uint32_t bh[4];
                    ldm4(bh, w2B + (uint32_t)(n16 * 16 * W2_PITCH + kb * 16) * 2);
                    mma16816(acc2[2 * n16],     afh[kb], bh[0], bh[1]);
                    mma16816(acc2[2 * n16 + 1], afh[kb], bh[2], bh[3]);
                }
            }
        }

        // ---- end of i-phase: gate = sigmoid(acc2 + bi2), reset acc2 ----
        if (c == 7) {
            #pragma unroll
            for (int t = 0; t < 16; t++) {
                int col = 8 * t + 2 * cq;
                float z0 = b2s[col], z1 = b2s[col + 1];
                gate[t][0] = 1.f / (1.f + __expf(-(acc2[t][0] + z0)));
                gate[t][1] = 1.f / (1.f + __expf(-(acc2[t][1] + z1)));
                gate[t][2] = 1.f / (1.f + __expf(-(acc2[t][2] + z0)));
                gate[t][3] = 1.f / (1.f + __expf(-(acc2[t][3] + z1)));
                acc2[t][0] = acc2[t][1] = acc2[t][2] = acc2[t][3] = 0.f;
            }
        }
    }

    __syncthreads();   // all MMA reads of W1 bufs done before aliasing as scatter buffer

    // ---- Rv = gate * (jv + bj2) -> SMEM (two 64-col halves) -> merged scatter ----
    float* rvb = (float*)(sm + OFF_W1B0);
    const int rA = row0 + rql, rB = rA + 8;
    #pragma unroll 1
    for (int hh = 0; hh < 2; hh++) {
        #pragma unroll
        for (int t = 0; t < 8; t++) {
            int tt = hh * 8 + t;
            int gcol = 8 * tt + 2 * cq;
            float z0 = b2s[128 + gcol], z1 = b2s[128 + gcol + 1];
            float v0 = gate[tt][0] * (acc2[tt][0] + z0);
            float v1 = gate[tt][1] * (acc2[tt][1] + z1);
            float v2 = gate[tt][2] * (acc2[tt][2] + z0);
            float v3 = gate[tt][3] * (acc2[tt][3] + z1);
            int lcol = 8 * t + 2 * cq;
            rvb[rA * RV_PITCH + lcol]     = v0;
            rvb[rA * RV_PITCH + lcol + 1] = v1;
            rvb[rB * RV_PITCH + lcol]     = v2;
            rvb[rB * RV_PITCH + lcol + 1] = v3;
        }
        __syncthreads();
        {
            int col = tid & 63, rg = tid >> 6;   // rg in {0,1}, 32 rows each
            float sum = 0.f; int cur = -1;
            for (int r = rg * 32; r < rg * 32 + 32; r++) {
                int m = m0 + r;
                if (m >= M_NODES) break;
                int g = sgi[r];
                float v = rvb[r * RV_PITCH + col];
                if (g != cur) {
                    if (cur >= 0) atomicAdd(&R[(size_t)cur * 128 + hh * 64 + col], sum);
                    cur = g; sum = v;
                } else sum += v;
            }
            if (cur >= 0) atomicAdd(&R[(size_t)cur * 128 + hh * 64 + col], sum);
        }
        __syncthreads();
    }
}

// ---------------- launch ----------------
extern "C" void kernel_launch(void* const* d_in, const int* in_sizes, int n_in,
                              void* d_out, int out_size) {
    const float* h_T = (const float*)d_in[0];
    const float* h_0 = (const float*)d_in[1];
    const int*   gix = (const int*)d_in[2];
    const float* Wi1 = (const float*)d_in[3];
    const float* bi1 = (const float*)d_in[4];
    const float* Wi2 = (const float*)d_in[5];
    const float* bi2 = (const float*)d_in[6];
    const float* Wj1 = (const float*)d_in[7];
    const float* bj1 = (const float*)d_in[8];
    const float* Wj2 = (const float*)d_in[9];
    const float* bj2 = (const float*)d_in[10];
    float* R = (float*)d_out;

    cudaFuncSetAttribute(fused_kernel, cudaFuncAttributeMaxDynamicSharedMemorySize, SMEM_BYTES);

    int prep_elems = 512 * 256 + 512 * 128 + 2 * 128 * 512;
    prep_kernel<<<(prep_elems + 255) / 256, 256>>>(Wi1, Wj1, Wi2, Wj2);
    zero_out_kernel<<<(NGRAPH * 128 + 255) / 256, 256>>>(R, NGRAPH * 128);
    fused_kernel<<<NTILES, NT, SMEM_BYTES>>>(h_T, h_0, gix, bi1, bj1, bi2, bj2, R);
}

// round 10
// speedup vs baseline: 5.2483x; 1.0637x over previous
#include <cuda_runtime.h>
#include <cuda_fp16.h>
#include <cstdint>

#define M_NODES 200000
#define NGRAPH  1024
#define NT      128
#define BM      64
#define NTILES  ((M_NODES + BM - 1) / BM)   // 3125

// ---- SMEM layout (bytes) ----
#define OFF_X     0          // 64 x 264 half = 33792 (cols 0-127 hT, 128-255 h0; h0 area reused as fp16 gate after i-phase)
#define X_PITCH   264
#define OFF_W1B0  33792      // 64 x 136 half = 17408 (double-buffered W1)
#define OFF_W1B1  51200
#define W1_PITCH  136
#define OFF_W2B0  68608      // 128 x 72 half = 18432 (double-buffered W2)
#define OFF_W2B1  87040
#define W2_PITCH  72
#define OFF_B1    105472     // 1024 f32
#define OFF_B2    109568     // 256 f32
#define OFF_GI    110592     // 64 int
#define SMEM_BYTES 110848
#define RV_PITCH  68         // fp32 scatter buffer aliased at OFF_W1B0 (64*68*4 = 17408 = one W1 buf)

// ---- pre-rounded fp16 weights, [n][k] row-major ----
__device__ __half g_w1i[512 * 256];
__device__ __half g_w1j[512 * 128];
__device__ __half g_w2i[128 * 512];
__device__ __half g_w2j[128 * 512];

__device__ __forceinline__ uint32_t smem_u32(const void* p) {
    uint32_t a;
    asm("{ .reg .u64 t; cvta.to.shared.u64 t, %1; cvt.u32.u64 %0, t; }" : "=r"(a) : "l"(p));
    return a;
}
__device__ __forceinline__ void ldm4(uint32_t r[4], uint32_t addr) {
    asm volatile("ldmatrix.sync.aligned.m8n8.x4.shared.b16 {%0,%1,%2,%3}, [%4];"
        : "=r"(r[0]), "=r"(r[1]), "=r"(r[2]), "=r"(r[3]) : "r"(addr));
}
__device__ __forceinline__ void mma16816(float d[4], const uint32_t a[4],
                                         uint32_t b0, uint32_t b1) {
    asm volatile("mma.sync.aligned.m16n8k16.row.col.f32.f16.f16.f32 "
        "{%0,%1,%2,%3}, {%4,%5,%6,%7}, {%8,%9}, {%0,%1,%2,%3};"
        : "+f"(d[0]), "+f"(d[1]), "+f"(d[2]), "+f"(d[3])
        : "r"(a[0]), "r"(a[1]), "r"(a[2]), "r"(a[3]), "r"(b0), "r"(b1));
}
__device__ __forceinline__ void cpasync16(uint32_t dst, const void* src) {
    asm volatile("cp.async.cg.shared.global [%0], [%1], 16;" :: "r"(dst), "l"(src) : "memory");
}

// ---------- setup: zero output + round weights to fp16, transpose to [n][k] ----------
__global__ void setup_kernel(const float* __restrict__ Wi1, const float* __restrict__ Wj1,
                             const float* __restrict__ Wi2, const float* __restrict__ Wj2,
                             float* __restrict__ R) {
    int idx = blockIdx.x * blockDim.x + threadIdx.x;
    if (idx < NGRAPH * 128) R[idx] = 0.0f;
    if (idx < 512 * 256) {
        int n = idx >> 8, k = idx & 255;
        g_w1i[idx] = __float2half(Wi1[(size_t)k * 512 + n]);
    } else if (idx < 512 * 256 + 512 * 128) {
        int j = idx - 512 * 256; int n = j >> 7, k = j & 127;
        g_w1j[j] = __float2half(Wj1[(size_t)k * 512 + n]);
    } else if (idx < 512 * 256 + 512 * 128 + 128 * 512) {
        int j = idx - 512 * 256 - 512 * 128; int n = j >> 9, k = j & 511;
        g_w2i[j] = __float2half(Wi2[(size_t)k * 128 + n]);
    } else if (idx < 512 * 256 + 512 * 128 + 2 * 128 * 512) {
        int j = idx - 512 * 256 - 512 * 128 - 128 * 512; int n = j >> 9, k = j & 511;
        g_w2j[j] = __float2half(Wj2[(size_t)k * 128 + n]);
    }
}

// stage unit u (0..23): W1 slice (+W2 on first slice of a chunk) via cp.async; always commit.
// u<16: chunk c=u>>1 (i-path), slice s=u&1.  u>=16: chunk c=u-8 (j-path), s=0.
__device__ __forceinline__ void issue_stage(int u, uint32_t su, int tid) {
    if (u < 24) {
        int c, s;
        if (u < 16) { c = u >> 1; s = u & 1; } else { c = u - 8; s = 0; }
        const bool ipath = (c < 8);
        const int kst = ipath ? 256 : 128;
        const __half* src1 = ipath ? (g_w1i + (size_t)c * 64 * 256 + s * 128)
                                   : (g_w1j + (size_t)(c - 8) * 64 * 128);
        uint32_t dst1 = su + ((u & 1) ? OFF_W1B1 : OFF_W1B0);
        #pragma unroll
        for (int j = 0; j < 8; j++) {
            int idx = tid + j * NT;
            int r = idx >> 4, q = idx & 15;
            cpasync16(dst1 + (uint32_t)(r * (W1_PITCH * 2) + q * 16),
                      src1 + (size_t)r * kst + q * 8);
        }
        if (s == 0) {
            const __half* src2 = (ipath ? g_w2i : g_w2j) + (c & 7) * 64;
            uint32_t dst2 = su + ((c & 1) ? OFF_W2B1 : OFF_W2B0);
            #pragma unroll
            for (int j = 0; j < 8; j++) {
                int idx = tid + j * NT;
                int r = idx >> 3, q = idx & 7;
                cpasync16(dst2 + (uint32_t)(r * (W2_PITCH * 2) + q * 16),
                          src2 + (size_t)r * 512 + q * 8);
            }
        }
    }
    asm volatile("cp.async.commit_group;" ::: "memory");
}

// ---------- fused MLP + gate + segment-sum ----------
__global__ __launch_bounds__(NT, 2)
void fused_kernel(const float* __restrict__ hT, const float* __restrict__ h0,
                  const int* __restrict__ gidx,
                  const float* __restrict__ bi1, const float* __restrict__ bj1,
                  const float* __restrict__ bi2, const float* __restrict__ bj2,
                  float* __restrict__ R) {
    extern __shared__ char sm[];
    const uint32_t su = smem_u32(sm);
    const int tid = threadIdx.x;
    const int wid = tid >> 5, lane = tid & 31;
    const int m0 = blockIdx.x * BM;
    const int row0 = wid * 16;
    const int cq = lane & 3;
    const int rql = lane >> 2;

    float* b1s = (float*)(sm + OFF_B1);
    float* b2s = (float*)(sm + OFF_B2);
    int*   sgi = (int*)(sm + OFF_GI);

    // ---- stage bias / gidx ----
    for (int i = tid; i < 1024; i += NT) b1s[i] = (i < 512) ? bi1[i] : bj1[i - 512];
    for (int i = tid; i < 256;  i += NT) b2s[i] = (i < 128) ? bi2[i] : bj2[i - 128];
    if (tid < BM) { int m = m0 + tid; sgi[tid] = (m < M_NODES) ? gidx[m] : 0; }

    // ---- stage X = [hT|h0] fp16 into SMEM (64 rows, 128 threads) ----
    {
        int m = m0 + (tid >> 1);
        int hf = tid & 1;
        bool valid = (m < M_NODES);
        __half2* xrow = (__half2*)(sm + OFF_X);
        #pragma unroll
        for (int src = 0; src < 2; src++) {
            const float* p = (src ? h0 : hT) + (size_t)m * 128 + hf * 64;
            int hib = src * 128 + hf * 64;
            #pragma unroll
            for (int q = 0; q < 16; q++) {
                float4 v = valid ? ((const float4*)p)[q] : make_float4(0.f, 0.f, 0.f, 0.f);
                __half2 h0p = __floats2half2_rn(v.x, v.y);
                __half2 h1p = __floats2half2_rn(v.z, v.w);
                size_t base = (size_t)(tid >> 1) * (X_PITCH / 2);
                xrow[base + (hib >> 1) + 2 * q]     = h0p;
                xrow[base + (hib >> 1) + 2 * q + 1] = h1p;
            }
        }
    }

    // kick off first weight stage (group 0) — independent of X staging region
    issue_stage(0, su, tid);

    // ldmatrix lane address components
    const int arow = row0 + (lane & 15);
    const int acolo = (lane >> 4) << 3;
    const int bn = (lane & 7) + ((lane >> 4) << 3);
    const int bk = ((lane >> 3) & 1) << 3;
    const uint32_t xAaddr = su + (uint32_t)(arow * X_PITCH) * 2;
    const uint32_t w1B0 = su + OFF_W1B0 + (uint32_t)(bn * W1_PITCH + bk) * 2;
    const uint32_t w1B1 = su + OFF_W1B1 + (uint32_t)(bn * W1_PITCH + bk) * 2;
    const uint32_t w2B0 = su + OFF_W2B0 + (uint32_t)(bn * W2_PITCH + bk) * 2;
    const uint32_t w2B1 = su + OFF_W2B1 + (uint32_t)(bn * W2_PITCH + bk) * 2;

    float acc2[16][4];
    #pragma unroll
    for (int t = 0; t < 16; t++)
        #pragma unroll
        for (int q = 0; q < 4; q++) acc2[t][q] = 0.f;

    int u = 0;
    #pragma unroll 1
    for (int c = 0; c < 16; c++) {
        const bool ipath = (c < 8);
        const int c8 = c & 7;

        float acc1[8][4];
        #pragma unroll
        for (int t = 0; t < 8; t++)
            #pragma unroll
            for (int q = 0; q < 4; q++) acc1[t][q] = 0.f;

        const int nsl = ipath ? 2 : 1;
        #pragma unroll 1
        for (int s = 0; s < nsl; s++, u++) {
            asm volatile("cp.async.wait_group 0;" ::: "memory");  // unit u landed
            __syncthreads();            // visible to all; all warps done with buffer u-1
            issue_stage(u + 1, su, tid);  // stream unit u+1 into buffer u-1 while we compute

            const uint32_t wB = (u & 1) ? w1B1 : w1B0;
            #pragma unroll
            for (int k16 = 0; k16 < 8; k16++) {
                uint32_t ahi[4];
                int colh = s * 128 + k16 * 16 + acolo;
                ldm4(ahi, xAaddr + (uint32_t)colh * 2);
                #pragma unroll
                for (int n16 = 0; n16 < 4; n16++) {
                    uint32_t bh[4];
                    ldm4(bh, wB + (uint32_t)(n16 * 16 * W1_PITCH + k16 * 16) * 2);
                    mma16816(acc1[2 * n16],     ahi, bh[0], bh[1]);
                    mma16816(acc1[2 * n16 + 1], ahi, bh[2], bh[3]);
                }
            }
        }

        // ---- epilogue: bias + ReLU + fp16 round -> layer-2 A-frags ----
        uint32_t afh[4][4];
        {
            const int bb = (ipath ? 0 : 512) + c8 * 64 + 2 * cq;
            #pragma unroll
            for (int t = 0; t < 8; t++) {
                float bz0 = b1s[bb + 8 * t], bz1 = b1s[bb + 8 * t + 1];
                float x0 = fmaxf(acc1[t][0] + bz0, 0.f);
                float x1 = fmaxf(acc1[t][1] + bz1, 0.f);
                float x2 = fmaxf(acc1[t][2] + bz0, 0.f);
                float x3 = fmaxf(acc1[t][3] + bz1, 0.f);
                __half2 h01 = __floats2half2_rn(x0, x1);
                __half2 h23 = __floats2half2_rn(x2, x3);
                int kb = t >> 1, off = (t & 1) * 2;
                afh[kb][off]     = *(uint32_t*)&h01;
                afh[kb][off + 1] = *(uint32_t*)&h23;
            }
        }

        // ---- MMA2: acc2 += Y @ W2chunk ----
        {
            const uint32_t w2B = (c & 1) ? w2B1 : w2B0;
            #pragma unroll
            for (int kb = 0; kb < 4; kb++) {
                #pragma unroll
                for (int n16 = 0; n16 < 8; n16++) {
                    uint32_t bh[4];
                    ldm4(bh, w2B + (uint32_t)(n16 * 16 * W2_PITCH + kb * 16) * 2);
                    mma16816(acc2[2 * n16],     afh[kb], bh[0], bh[1]);
                    mma16816(acc2[2 * n16 + 1], afh[kb], bh[2], bh[3]);
                }
            }
        }

        // ---- end of i-phase: gate = sigmoid(acc2 + bi2) -> fp16 in X's h0 area; reset acc2 ----
        // j-path reads only hT columns (0-127) of X; columns 128-255 are dead -> store gate there.
        // A-fragment rows are warp-private, so writing our own rows is race-free.
        if (c == 7) {
            const int rA = row0 + rql, rB = rA + 8;
            #pragma unroll
            for (int t = 0; t < 16; t++) {
                int col = 8 * t + 2 * cq;
                float z0 = b2s[col], z1 = b2s[col + 1];
                float g0 = 1.f / (1.f + __expf(-(acc2[t][0] + z0)));
                float g1 = 1.f / (1.f + __expf(-(acc2[t][1] + z1)));
                float g2 = 1.f / (1.f + __expf(-(acc2[t][2] + z0)));
                float g3 = 1.f / (1.f + __expf(-(acc2[t][3] + z1)));
                *(__half2*)(sm + OFF_X + rA * (X_PITCH * 2) + (128 + col) * 2) = __floats2half2_rn(g0, g1);
                *(__half2*)(sm + OFF_X + rB * (X_PITCH * 2) + (128 + col) * 2) = __floats2half2_rn(g2, g3);
                acc2[t][0] = acc2[t][1] = acc2[t][2] = acc2[t][3] = 0.f;
            }
        }
    }

    __syncthreads();   // all MMA reads of W1 bufs done before aliasing as scatter buffer

    // ---- Rv = gate * (jv + bj2) -> SMEM (two 64-col halves) -> merged scatter ----
    float* rvb = (float*)(sm + OFF_W1B0);
    const int rA = row0 + rql, rB = rA + 8;
    #pragma unroll 1
    for (int hh = 0; hh < 2; hh++) {
        #pragma unroll
        for (int t = 0; t < 8; t++) {
            int tt = hh * 8 + t;
            int gcol = 8 * tt + 2 * cq;
            float z0 = b2s[128 + gcol], z1 = b2s[128 + gcol + 1];
            __half2 gA = *(__half2*)(sm + OFF_X + rA * (X_PITCH * 2) + (128 + gcol) * 2);
            __half2 gB = *(__half2*)(sm + OFF_X + rB * (X_PITCH * 2) + (128 + gcol) * 2);
            float v0 = __half2float(__low2half(gA))  * (acc2[tt][0] + z0);
            float v1 = __half2float(__high2half(gA)) * (acc2[tt][1] + z1);
            float v2 = __half2float(__low2half(gB))  * (acc2[tt][2] + z0);
            float v3 = __half2float(__high2half(gB)) * (acc2[tt][3] + z1);
            int lcol = 8 * t + 2 * cq;
            rvb[rA * RV_PITCH + lcol]     = v0;
            rvb[rA * RV_PITCH + lcol + 1] = v1;
            rvb[rB * RV_PITCH + lcol]     = v2;
            rvb[rB * RV_PITCH + lcol + 1] = v3;
        }
        __syncthreads();
        {
            int col = tid & 63, rg = tid >> 6;   // rg in {0,1}, 32 rows each
            float sum = 0.f; int cur = -1;
            for (int r = rg * 32; r < rg * 32 + 32; r++) {
                int m = m0 + r;
                if (m >= M_NODES) break;
                int g = sgi[r];
                float v = rvb[r * RV_PITCH + col];
                if (g != cur) {
                    if (cur >= 0) atomicAdd(&R[(size_t)cur * 128 + hh * 64 + col], sum);
                    cur = g; sum = v;
                } else sum += v;
            }
            if (cur >= 0) atomicAdd(&R[(size_t)cur * 128 + hh * 64 + col], sum);
        }
        __syncthreads();
    }
}

// ---------------- launch ----------------
extern "C" void kernel_launch(void* const* d_in, const int* in_sizes, int n_in,
                              void* d_out, int out_size) {
    const float* h_T = (const float*)d_in[0];
    const float* h_0 = (const float*)d_in[1];
    const int*   gix = (const int*)d_in[2];
    const float* Wi1 = (const float*)d_in[3];
    const float* bi1 = (const float*)d_in[4];
    const float* Wi2 = (const float*)d_in[5];
    const float* bi2 = (const float*)d_in[6];
    const float* Wj1 = (const float*)d_in[7];
    const float* bj1 = (const float*)d_in[8];
    const float* Wj2 = (const float*)d_in[9];
    const float* bj2 = (const float*)d_in[10];
    float* R = (float*)d_out;

    cudaFuncSetAttribute(fused_kernel, cudaFuncAttributeMaxDynamicSharedMemorySize, SMEM_BYTES);

    int setup_elems = 512 * 256 + 512 * 128 + 2 * 128 * 512;   // >= NGRAPH*128
    setup_kernel<<<(setup_elems + 255) / 256, 256>>>(Wi1, Wj1, Wi2, Wj2, R);
    fused_kernel<<<NTILES, NT, SMEM_BYTES>>>(h_T, h_0, gix, bi1, bj1, bi2, bj2, R);
}

// round 11
// speedup vs baseline: 5.9098x; 1.1260x over previous
#include <cuda_runtime.h>
#include <cuda_fp16.h>
#include <cstdint>

#define M_NODES 200000
#define NGRAPH  1024
#define NT      256
#define BM      64
#define NTILES  ((M_NODES + BM - 1) / BM)   // 3125

// ---- SMEM layout (bytes) ----
#define OFF_X     0          // 64 x 264 half = 33792 (cols 0-127 hT, 128-255 h0; h0 area reused as fp16 gate after i-phase)
#define X_PITCH   264
#define OFF_W1B0  33792      // 64 x 136 half = 17408 (double-buffered W1)
#define OFF_W1B1  51200
#define W1_PITCH  136
#define OFF_W2B0  68608      // 128 x 72 half = 18432 (double-buffered W2)
#define OFF_W2B1  87040
#define W2_PITCH  72
#define OFF_Y     105472     // 64 x 72 half = 9216 (layer-1 output exchange)
#define Y_PITCH   72
#define OFF_GI    114688     // 64 int
#define SMEM_BYTES 114944    // x2 CTAs = 229888 <= 228KB/SM
#define RV_PITCH  132        // fp32 scatter buffer aliased over both W1 bufs (64*132*4 = 33792 <= 34816)

// ---- pre-rounded fp16 weights, [n][k] row-major ----
__device__ __half g_w1i[512 * 256];
__device__ __half g_w1j[512 * 128];
__device__ __half g_w2i[128 * 512];
__device__ __half g_w2j[128 * 512];

__device__ __forceinline__ uint32_t smem_u32(const void* p) {
    uint32_t a;
    asm("{ .reg .u64 t; cvta.to.shared.u64 t, %1; cvt.u32.u64 %0, t; }" : "=r"(a) : "l"(p));
    return a;
}
__device__ __forceinline__ void ldm4(uint32_t r[4], uint32_t addr) {
    asm volatile("ldmatrix.sync.aligned.m8n8.x4.shared.b16 {%0,%1,%2,%3}, [%4];"
        : "=r"(r[0]), "=r"(r[1]), "=r"(r[2]), "=r"(r[3]) : "r"(addr));
}
__device__ __forceinline__ void mma16816(float d[4], const uint32_t a[4],
                                         uint32_t b0, uint32_t b1) {
    asm volatile("mma.sync.aligned.m16n8k16.row.col.f32.f16.f16.f32 "
        "{%0,%1,%2,%3}, {%4,%5,%6,%7}, {%8,%9}, {%0,%1,%2,%3};"
        : "+f"(d[0]), "+f"(d[1]), "+f"(d[2]), "+f"(d[3])
        : "r"(a[0]), "r"(a[1]), "r"(a[2]), "r"(a[3]), "r"(b0), "r"(b1));
}
__device__ __forceinline__ void cpasync16(uint32_t dst, const void* src) {
    asm volatile("cp.async.cg.shared.global [%0], [%1], 16;" :: "r"(dst), "l"(src) : "memory");
}

// ---------- setup: zero output + round weights to fp16, transpose to [n][k] ----------
__global__ void setup_kernel(const float* __restrict__ Wi1, const float* __restrict__ Wj1,
                             const float* __restrict__ Wi2, const float* __restrict__ Wj2,
                             float* __restrict__ R) {
    int idx = blockIdx.x * blockDim.x + threadIdx.x;
    if (idx < NGRAPH * 128) R[idx] = 0.0f;
    if (idx < 512 * 256) {
        int n = idx >> 8, k = idx & 255;
        g_w1i[idx] = __float2half(Wi1[(size_t)k * 512 + n]);
    } else if (idx < 512 * 256 + 512 * 128) {
        int j = idx - 512 * 256; int n = j >> 7, k = j & 127;
        g_w1j[j] = __float2half(Wj1[(size_t)k * 512 + n]);
    } else if (idx < 512 * 256 + 512 * 128 + 128 * 512) {
        int j = idx - 512 * 256 - 512 * 128; int n = j >> 9, k = j & 511;
        g_w2i[j] = __float2half(Wi2[(size_t)k * 128 + n]);
    } else if (idx < 512 * 256 + 512 * 128 + 2 * 128 * 512) {
        int j = idx - 512 * 256 - 512 * 128 - 128 * 512; int n = j >> 9, k = j & 511;
        g_w2j[j] = __float2half(Wj2[(size_t)k * 128 + n]);
    }
}

// stage unit u (0..23): W1 slice (+W2 on first slice of a chunk) via cp.async; always commit.
// u<16: chunk c=u>>1 (i-path), slice s=u&1.  u>=16: chunk c=u-8 (j-path), s=0.
__device__ __forceinline__ void issue_stage(int u, uint32_t su, int tid) {
    if (u < 24) {
        int c, s;
        if (u < 16) { c = u >> 1; s = u & 1; } else { c = u - 8; s = 0; }
        const bool ipath = (c < 8);
        const int kst = ipath ? 256 : 128;
        const __half* src1 = ipath ? (g_w1i + (size_t)c * 64 * 256 + s * 128)
                                   : (g_w1j + (size_t)(c - 8) * 64 * 128);
        uint32_t dst1 = su + ((u & 1) ? OFF_W1B1 : OFF_W1B0);
        #pragma unroll
        for (int j = 0; j < 4; j++) {
            int idx = tid + j * NT;
            int r = idx >> 4, q = idx & 15;
            cpasync16(dst1 + (uint32_t)(r * (W1_PITCH * 2) + q * 16),
                      src1 + (size_t)r * kst + q * 8);
        }
        if (s == 0) {
            const __half* src2 = (ipath ? g_w2i : g_w2j) + (c & 7) * 64;
            uint32_t dst2 = su + ((c & 1) ? OFF_W2B1 : OFF_W2B0);
            #pragma unroll
            for (int j = 0; j < 4; j++) {
                int idx = tid + j * NT;
                int r = idx >> 3, q = idx & 7;
                cpasync16(dst2 + (uint32_t)(r * (W2_PITCH * 2) + q * 16),
                          src2 + (size_t)r * 512 + q * 8);
            }
        }
    }
    asm volatile("cp.async.commit_group;" ::: "memory");
}

// ---------- fused MLP + gate + segment-sum ----------
// Warp decomposition: wid 0-7; rowgrp = wid&3 (16 rows each), nh = wid>>2 (64-col output half).
__global__ __launch_bounds__(NT, 2)
void fused_kernel(const float* __restrict__ hT, const float* __restrict__ h0,
                  const int* __restrict__ gidx,
                  const float* __restrict__ bi1, const float* __restrict__ bj1,
                  const float* __restrict__ bi2, const float* __restrict__ bj2,
                  float* __restrict__ R) {
    extern __shared__ char sm[];
    const uint32_t su = smem_u32(sm);
    const int tid = threadIdx.x;
    const int wid = tid >> 5, lane = tid & 31;
    const int rowgrp = wid & 3, nh = wid >> 2;
    const int row0 = rowgrp * 16;
    const int m0 = blockIdx.x * BM;
    const int cq = lane & 3;
    const int rql = lane >> 2;

    int* sgi = (int*)(sm + OFF_GI);
    if (tid < BM) { int m = m0 + tid; sgi[tid] = (m < M_NODES) ? gidx[m] : 0; }

    // ---- stage X = [hT|h0] fp16 into SMEM (64 rows, 256 threads: 4 per row) ----
    {
        int m = m0 + (tid >> 2);
        int sub = tid & 3;
        int srcsel = sub >> 1, hf = sub & 1;
        bool valid = (m < M_NODES);
        const float* p = (srcsel ? h0 : hT) + (size_t)m * 128 + hf * 64;
        int hib = srcsel * 128 + hf * 64;
        __half2* xrow = (__half2*)(sm + OFF_X) + (size_t)(tid >> 2) * (X_PITCH / 2);
        #pragma unroll
        for (int q = 0; q < 16; q++) {
            float4 v = valid ? ((const float4*)p)[q] : make_float4(0.f, 0.f, 0.f, 0.f);
            xrow[(hib >> 1) + 2 * q]     = __floats2half2_rn(v.x, v.y);
            xrow[(hib >> 1) + 2 * q + 1] = __floats2half2_rn(v.z, v.w);
        }
    }

    // kick off first weight stage (group 0) — independent of X staging region
    issue_stage(0, su, tid);

    // ldmatrix lane address components
    const int arow = row0 + (lane & 15);
    const int acolo = (lane >> 4) << 3;
    const int bn = (lane & 7) + ((lane >> 4) << 3);
    const int bk = ((lane >> 3) & 1) << 3;
    const uint32_t xAaddr = su + (uint32_t)(arow * X_PITCH) * 2;
    const uint32_t yAaddr = su + OFF_Y + (uint32_t)(arow * Y_PITCH + acolo) * 2;
    const uint32_t w1B0 = su + OFF_W1B0 + (uint32_t)((nh * 32 + bn) * W1_PITCH + bk) * 2;
    const uint32_t w1B1 = su + OFF_W1B1 + (uint32_t)((nh * 32 + bn) * W1_PITCH + bk) * 2;
    const uint32_t w2B0 = su + OFF_W2B0 + (uint32_t)((nh * 64 + bn) * W2_PITCH + bk) * 2;
    const uint32_t w2B1 = su + OFF_W2B1 + (uint32_t)((nh * 64 + bn) * W2_PITCH + bk) * 2;

    const int rA = row0 + rql, rB = rA + 8;

    float acc2[8][4];
    #pragma unroll
    for (int t = 0; t < 8; t++)
        #pragma unroll
        for (int q = 0; q < 4; q++) acc2[t][q] = 0.f;

    int u = 0;
    #pragma unroll 1
    for (int c = 0; c < 16; c++) {
        const bool ipath = (c < 8);
        const int c8 = c & 7;

        float acc1[4][4];
        #pragma unroll
        for (int t = 0; t < 4; t++)
            #pragma unroll
            for (int q = 0; q < 4; q++) acc1[t][q] = 0.f;

        const int nsl = ipath ? 2 : 1;
        #pragma unroll 1
        for (int s = 0; s < nsl; s++, u++) {
            asm volatile("cp.async.wait_group 0;" ::: "memory");  // unit u landed
            __syncthreads();              // all warps past prior reads of target buffers
            issue_stage(u + 1, su, tid);  // stream next unit while we compute

            const uint32_t wB = (u & 1) ? w1B1 : w1B0;
            #pragma unroll
            for (int k16 = 0; k16 < 8; k16++) {
                uint32_t ah[4];
                int colh = s * 128 + k16 * 16 + acolo;
                ldm4(ah, xAaddr + (uint32_t)colh * 2);
                #pragma unroll
                for (int g = 0; g < 2; g++) {
                    uint32_t bh[4];
                    ldm4(bh, wB + (uint32_t)(g * 16 * W1_PITCH + k16 * 16) * 2);
                    mma16816(acc1[2 * g],     ah, bh[0], bh[1]);
                    mma16816(acc1[2 * g + 1], ah, bh[2], bh[3]);
                }
            }
        }

        // ---- epilogue: bias + ReLU + fp16 round -> Y SMEM (warp's 16 rows x 32 cols) ----
        {
            const float* bsrc = ipath ? bi1 : bj1;
            const int bb = c8 * 64 + nh * 32 + 2 * cq;
            #pragma unroll
            for (int t = 0; t < 4; t++) {
                float bz0 = bsrc[bb + 8 * t], bz1 = bsrc[bb + 8 * t + 1];
                float x0 = fmaxf(acc1[t][0] + bz0, 0.f);
                float x1 = fmaxf(acc1[t][1] + bz1, 0.f);
                float x2 = fmaxf(acc1[t][2] + bz0, 0.f);
                float x3 = fmaxf(acc1[t][3] + bz1, 0.f);
                int ycol = nh * 32 + 8 * t + 2 * cq;
                *(__half2*)(sm + OFF_Y + (rA * Y_PITCH + ycol) * 2) = __floats2half2_rn(x0, x1);
                *(__half2*)(sm + OFF_Y + (rB * Y_PITCH + ycol) * 2) = __floats2half2_rn(x2, x3);
            }
        }
        __syncthreads();   // Y halves exchanged between nh warps of each row group

        // ---- MMA2: acc2 += Y @ W2chunk (warp: 16 rows x 64 out cols) ----
        {
            const uint32_t w2B = (c & 1) ? w2B1 : w2B0;
            #pragma unroll
            for (int kb = 0; kb < 4; kb++) {
                uint32_t ah[4];
                ldm4(ah, yAaddr + (uint32_t)(kb * 16) * 2);
                #pragma unroll
                for (int g = 0; g < 4; g++) {
                    uint32_t bh[4];
                    ldm4(bh, w2B + (uint32_t)(g * 16 * W2_PITCH + kb * 16) * 2);
                    mma16816(acc2[2 * g],     ah, bh[0], bh[1]);
                    mma16816(acc2[2 * g + 1], ah, bh[2], bh[3]);
                }
            }
        }

        // ---- end of i-phase: gate = sigmoid(acc2 + bi2) -> fp16 in X's h0 area; reset acc2 ----
        // j-path reads only hT columns (0-127) of X; columns 128-255 are dead.
        if (c == 7) {
            #pragma unroll
            for (int t = 0; t < 8; t++) {
                int gcol = nh * 64 + 8 * t + 2 * cq;
                float z0 = bi2[gcol], z1 = bi2[gcol + 1];
                float g0 = 1.f / (1.f + __expf(-(acc2[t][0] + z0)));
                float g1 = 1.f / (1.f + __expf(-(acc2[t][1] + z1)));
                float g2 = 1.f / (1.f + __expf(-(acc2[t][2] + z0)));
                float g3 = 1.f / (1.f + __expf(-(acc2[t][3] + z1)));
                *(__half2*)(sm + OFF_X + (rA * X_PITCH + 128 + gcol) * 2) = __floats2half2_rn(g0, g1);
                *(__half2*)(sm + OFF_X + (rB * X_PITCH + 128 + gcol) * 2) = __floats2half2_rn(g2, g3);
                acc2[t][0] = acc2[t][1] = acc2[t][2] = acc2[t][3] = 0.f;
            }
        }
    }

    // ---- Rv = gate * (jv + bj2) -> SMEM (64 x 132 f32 aliased over W1 bufs) ----
    // W1 buffers dead after last chunk's Y-exchange sync; each warp writes its own rows/cols.
    float* rvb = (float*)(sm + OFF_W1B0);
    #pragma unroll
    for (int t = 0; t < 8; t++) {
        int gcol = nh * 64 + 8 * t + 2 * cq;
        float z0 = bj2[gcol], z1 = bj2[gcol + 1];
        __half2 gA = *(__half2*)(sm + OFF_X + (rA * X_PITCH + 128 + gcol) * 2);
        __half2 gB = *(__half2*)(sm + OFF_X + (rB * X_PITCH + 128 + gcol) * 2);
        rvb[rA * RV_PITCH + gcol]     = __half2float(__low2half(gA))  * (acc2[t][0] + z0);
        rvb[rA * RV_PITCH + gcol + 1] = __half2float(__high2half(gA)) * (acc2[t][1] + z1);
        rvb[rB * RV_PITCH + gcol]     = __half2float(__low2half(gB))  * (acc2[t][2] + z0);
        rvb[rB * RV_PITCH + gcol + 1] = __half2float(__high2half(gB)) * (acc2[t][3] + z1);
    }
    __syncthreads();

    // ---- run-length merged scatter (graph_index sorted) ----
    {
        int col = tid & 127, rg = tid >> 7;   // rg in {0,1}, 32 rows each
        float sum = 0.f; int cur = -1;
        for (int r = rg * 32; r < rg * 32 + 32; r++) {
            int m = m0 + r;
            if (m >= M_NODES) break;
            int g = sgi[r];
            float v = rvb[r * RV_PITCH + col];
            if (g != cur) {
                if (cur >= 0) atomicAdd(&R[(size_t)cur * 128 + col], sum);
                cur = g; sum = v;
            } else sum += v;
        }
        if (cur >= 0) atomicAdd(&R[(size_t)cur * 128 + col], sum);
    }
}

// ---------------- launch ----------------
extern "C" void kernel_launch(void* const* d_in, const int* in_sizes, int n_in,
                              void* d_out, int out_size) {
    const float* h_T = (const float*)d_in[0];
    const float* h_0 = (const float*)d_in[1];
    const int*   gix = (const int*)d_in[2];
    const float* Wi1 = (const float*)d_in[3];
    const float* bi1 = (const float*)d_in[4];
    const float* Wi2 = (const float*)d_in[5];
    const float* bi2 = (const float*)d_in[6];
    const float* Wj1 = (const float*)d_in[7];
    const float* bj1 = (const float*)d_in[8];
    const float* Wj2 = (const float*)d_in[9];
    const float* bj2 = (const float*)d_in[10];
    float* R = (float*)d_out;

    cudaFuncSetAttribute(fused_kernel, cudaFuncAttributeMaxDynamicSharedMemorySize, SMEM_BYTES);

    int setup_elems = 512 * 256 + 512 * 128 + 2 * 128 * 512;   // >= NGRAPH*128
    setup_kernel<<<(setup_elems + 255) / 256, 256>>>(Wi1, Wj1, Wi2, Wj2, R);
    fused_kernel<<<NTILES, NT, SMEM_BYTES>>>(h_T, h_0, gix, bi1, bj1, bi2, bj2, R);
}

// round 16
// speedup vs baseline: 5.9581x; 1.0082x over previous
#include <cuda_runtime.h>
#include <cuda_fp16.h>
#include <cstdint>

#define M_NODES 200000
#define NGRAPH  1024
#define NT      256
#define BM      128
#define NTILES  ((M_NODES + BM - 1) / BM)   // 1563

// ---- SMEM layout (bytes) ----
#define OFF_X     0          // 128 x 264 half = 67584 (cols 0-127 hT, 128-255 h0; h0 area reused as fp16 gate)
#define X_PITCH   264
#define OFF_W1B0  67584      // 64 x 136 half = 17408 (double-buffered W1)
#define OFF_W1B1  84992
#define W1_PITCH  136
#define OFF_W2B0  102400     // 128 x 72 half = 18432 (double-buffered W2)
#define OFF_W2B1  120832
#define W2_PITCH  72
#define OFF_Y     139264     // 128 x 72 half = 18432 (layer-1 output exchange)
#define Y_PITCH   72
#define OFF_GI    157696     // 128 int
#define SMEM_BYTES 158208    // 1 CTA/SM
#define RV_PITCH  132        // fp32 scatter buffer aliased over W1B0..W2B1 (128*132*4 = 67584 <= 71680)

// ---- pre-rounded fp16 weights, [n][k] row-major ----
__device__ __half g_w1i[512 * 256];
__device__ __half g_w1j[512 * 128];
__device__ __half g_w2i[128 * 512];
__device__ __half g_w2j[128 * 512];

__device__ __forceinline__ uint32_t smem_u32(const void* p) {
    uint32_t a;
    asm("{ .reg .u64 t; cvta.to.shared.u64 t, %1; cvt.u32.u64 %0, t; }" : "=r"(a) : "l"(p));
    return a;
}
__device__ __forceinline__ void ldm4(uint32_t r[4], uint32_t addr) {
    asm volatile("ldmatrix.sync.aligned.m8n8.x4.shared.b16 {%0,%1,%2,%3}, [%4];"
        : "=r"(r[0]), "=r"(r[1]), "=r"(r[2]), "=r"(r[3]) : "r"(addr));
}
__device__ __forceinline__ void mma16816(float d[4], const uint32_t a[4],
                                         uint32_t b0, uint32_t b1) {
    asm volatile("mma.sync.aligned.m16n8k16.row.col.f32.f16.f16.f32 "
        "{%0,%1,%2,%3}, {%4,%5,%6,%7}, {%8,%9}, {%0,%1,%2,%3};"
        : "+f"(d[0]), "+f"(d[1]), "+f"(d[2]), "+f"(d[3])
        : "r"(a[0]), "r"(a[1]), "r"(a[2]), "r"(a[3]), "r"(b0), "r"(b1));
}
__device__ __forceinline__ void cpasync16(uint32_t dst, const void* src) {
    asm volatile("cp.async.cg.shared.global [%0], [%1], 16;" :: "r"(dst), "l"(src) : "memory");
}

// ---------- setup: zero output + round weights to fp16, transpose to [n][k] ----------
__global__ void setup_kernel(const float* __restrict__ Wi1, const float* __restrict__ Wj1,
                             const float* __restrict__ Wi2, const float* __restrict__ Wj2,
                             float* __restrict__ R) {
    int idx = blockIdx.x * blockDim.x + threadIdx.x;
    if (idx < NGRAPH * 128) R[idx] = 0.0f;
    if (idx < 512 * 256) {
        int n = idx >> 8, k = idx & 255;
        g_w1i[idx] = __float2half(Wi1[(size_t)k * 512 + n]);
    } else if (idx < 512 * 256 + 512 * 128) {
        int j = idx - 512 * 256; int n = j >> 7, k = j & 127;
        g_w1j[j] = __float2half(Wj1[(size_t)k * 512 + n]);
    } else if (idx < 512 * 256 + 512 * 128 + 128 * 512) {
        int j = idx - 512 * 256 - 512 * 128; int n = j >> 9, k = j & 511;
        g_w2i[j] = __float2half(Wi2[(size_t)k * 128 + n]);
    } else if (idx < 512 * 256 + 512 * 128 + 2 * 128 * 512) {
        int j = idx - 512 * 256 - 512 * 128 - 128 * 512; int n = j >> 9, k = j & 511;
        g_w2j[j] = __float2half(Wj2[(size_t)k * 128 + n]);
    }
}

// stage unit u (0..23): W1 slice (+W2 on first slice of a chunk) via cp.async; always commit.
// u<16: chunk c=u>>1 (i-path), slice s=u&1.  u>=16: chunk c=u-8 (j-path), s=0.
__device__ __forceinline__ void issue_stage(int u, uint32_t su, int tid) {
    if (u < 24) {
        int c, s;
        if (u < 16) { c = u >> 1; s = u & 1; } else { c = u - 8; s = 0; }
        const bool ipath = (c < 8);
        const int kst = ipath ? 256 : 128;
        const __half* src1 = ipath ? (g_w1i + (size_t)c * 64 * 256 + s * 128)
                                   : (g_w1j + (size_t)(c - 8) * 64 * 128);
        uint32_t dst1 = su + ((u & 1) ? OFF_W1B1 : OFF_W1B0);
        #pragma unroll
        for (int j = 0; j < 4; j++) {
            int idx = tid + j * NT;
            int r = idx >> 4, q = idx & 15;
            cpasync16(dst1 + (uint32_t)(r * (W1_PITCH * 2) + q * 16),
                      src1 + (size_t)r * kst + q * 8);
        }
        if (s == 0) {
            const __half* src2 = (ipath ? g_w2i : g_w2j) + (c & 7) * 64;
            uint32_t dst2 = su + ((c & 1) ? OFF_W2B1 : OFF_W2B0);
            #pragma unroll
            for (int j = 0; j < 4; j++) {
                int idx = tid + j * NT;
                int r = idx >> 3, q = idx & 7;
                cpasync16(dst2 + (uint32_t)(r * (W2_PITCH * 2) + q * 16),
                          src2 + (size_t)r * 512 + q * 8);
            }
        }
    }
    asm volatile("cp.async.commit_group;" ::: "memory");
}

// ---------- fused MLP + gate + segment-sum ----------
// 8 warps: rowgrp = wid&3 (32 rows), nh = wid>>2 (MMA1: 32 hidden cols; MMA2: 64 out cols).
__global__ __launch_bounds__(NT, 1)
void fused_kernel(const float* __restrict__ hT, const float* __restrict__ h0,
                  const int* __restrict__ gidx,
                  const float* __restrict__ bi1, const float* __restrict__ bj1,
                  const float* __restrict__ bi2, const float* __restrict__ bj2,
                  float* __restrict__ R) {
    extern __shared__ char sm[];
    const uint32_t su = smem_u32(sm);
    const int tid = threadIdx.x;
    const int wid = tid >> 5, lane = tid & 31;
    const int rowgrp = wid & 3, nh = wid >> 2;
    const int row0 = rowgrp * 32;
    const int m0 = blockIdx.x * BM;
    const int cq = lane & 3;
    const int rql = lane >> 2;

    int* sgi = (int*)(sm + OFF_GI);
    if (tid < BM) { int m = m0 + tid; sgi[tid] = (m < M_NODES) ? gidx[m] : 0; }

    // ---- stage X = [hT|h0] fp16 into SMEM (128 rows, 2 threads/row) ----
    {
        int m = m0 + (tid >> 1);
        int hf = tid & 1;
        bool valid = (m < M_NODES);
        __half2* xrow = (__half2*)(sm + OFF_X) + (size_t)(tid >> 1) * (X_PITCH / 2);
        #pragma unroll
        for (int src = 0; src < 2; src++) {
            const float* p = (src ? h0 : hT) + (size_t)m * 128 + hf * 64;
            int hib = src * 128 + hf * 64;
            #pragma unroll
            for (int q = 0; q < 16; q++) {
                float4 v = valid ? ((const float4*)p)[q] : make_float4(0.f, 0.f, 0.f, 0.f);
                xrow[(hib >> 1) + 2 * q]     = __floats2half2_rn(v.x, v.y);
                xrow[(hib >> 1) + 2 * q + 1] = __floats2half2_rn(v.z, v.w);
            }
        }
    }

    issue_stage(0, su, tid);
    __syncthreads();   // X (and sgi) visible to all warps

    // ldmatrix lane address components
    const int arow0 = row0 + (lane & 15);
    const int acolo = (lane >> 4) << 3;
    const int bn = (lane & 7) + ((lane >> 4) << 3);
    const int bk = ((lane >> 3) & 1) << 3;
    const uint32_t xA0 = su + (uint32_t)(arow0 * X_PITCH) * 2;
    const uint32_t xA1 = su + (uint32_t)((arow0 + 16) * X_PITCH) * 2;
    const uint32_t yA0 = su + OFF_Y + (uint32_t)(arow0 * Y_PITCH + acolo) * 2;
    const uint32_t yA1 = su + OFF_Y + (uint32_t)((arow0 + 16) * Y_PITCH + acolo) * 2;
    const uint32_t w1b0 = su + OFF_W1B0 + (uint32_t)((nh * 32 + bn) * W1_PITCH + bk) * 2;
    const uint32_t w1b1 = su + OFF_W1B1 + (uint32_t)((nh * 32 + bn) * W1_PITCH + bk) * 2;
    const uint32_t w2b0 = su + OFF_W2B0 + (uint32_t)((nh * 64 + bn) * W2_PITCH + bk) * 2;
    const uint32_t w2b1 = su + OFF_W2B1 + (uint32_t)((nh * 64 + bn) * W2_PITCH + bk) * 2;

    float acc2[16][4];
    #pragma unroll
    for (int t = 0; t < 16; t++)
        #pragma unroll
        for (int q = 0; q < 4; q++) acc2[t][q] = 0.f;

    int u = 0;
    #pragma unroll 1
    for (int c = 0; c < 16; c++) {
        const bool ipath = (c < 8);
        const int c8 = c & 7;

        float acc1[8][4];   // [m16*4 + n16g*2 + h]
        #pragma unroll
        for (int t = 0; t < 8; t++)
            #pragma unroll
            for (int q = 0; q < 4; q++) acc1[t][q] = 0.f;

        const int nsl = ipath ? 2 : 1;
        #pragma unroll 1
        for (int s = 0; s < nsl; s++, u++) {
            asm volatile("cp.async.wait_group 0;" ::: "memory");
            __syncthreads();
            issue_stage(u + 1, su, tid);

            const uint32_t wB = (u & 1) ? w1b1 : w1b0;
            #pragma unroll
            for (int k16 = 0; k16 < 8; k16++) {
                uint32_t a0[4], a1[4], b0[4], b1[4];
                uint32_t coff = (uint32_t)(s * 128 + k16 * 16 + acolo) * 2;
                ldm4(a0, xA0 + coff);
                ldm4(a1, xA1 + coff);
                ldm4(b0, wB + (uint32_t)(k16 * 16) * 2);
                ldm4(b1, wB + (uint32_t)(16 * W1_PITCH + k16 * 16) * 2);
                mma16816(acc1[0], a0, b0[0], b0[1]);
                mma16816(acc1[1], a0, b0[2], b0[3]);
                mma16816(acc1[2], a0, b1[0], b1[1]);
                mma16816(acc1[3], a0, b1[2], b1[3]);
                mma16816(acc1[4], a1, b0[0], b0[1]);
                mma16816(acc1[5], a1, b0[2], b0[3]);
                mma16816(acc1[6], a1, b1[0], b1[1]);
                mma16816(acc1[7], a1, b1[2], b1[3]);
            }
        }

        // ---- epilogue: bias + ReLU + fp16 round -> Y SMEM (warp: 32 rows x 32 cols) ----
        {
            const float* bsrc = ipath ? bi1 : bj1;
            #pragma unroll
            for (int f = 0; f < 8; f++) {
                int m16 = f >> 2, n16g = (f >> 1) & 1, h = f & 1;
                int col = nh * 32 + n16g * 16 + h * 8 + 2 * cq;
                float bz0 = bsrc[c8 * 64 + col], bz1 = bsrc[c8 * 64 + col + 1];
                int rA2 = row0 + m16 * 16 + rql, rB2 = rA2 + 8;
                float x0 = fmaxf(acc1[f][0] + bz0, 0.f);
                float x1 = fmaxf(acc1[f][1] + bz1, 0.f);
                float x2 = fmaxf(acc1[f][2] + bz0, 0.f);
                float x3 = fmaxf(acc1[f][3] + bz1, 0.f);
                *(__half2*)(sm + OFF_Y + (rA2 * Y_PITCH + col) * 2) = __floats2half2_rn(x0, x1);
                *(__half2*)(sm + OFF_Y + (rB2 * Y_PITCH + col) * 2) = __floats2half2_rn(x2, x3);
            }
        }
        __syncthreads();   // Y halves exchanged between nh warps

        // ---- MMA2: acc2 += Y @ W2chunk (warp: 32 rows x 64 out cols) ----
        {
            const uint32_t w2B = (c & 1) ? w2b1 : w2b0;
            #pragma unroll
            for (int kb = 0; kb < 4; kb++) {
                uint32_t ya0[4], ya1[4];
                ldm4(ya0, yA0 + (uint32_t)(kb * 16) * 2);
                ldm4(ya1, yA1 + (uint32_t)(kb * 16) * 2);
                #pragma unroll
                for (int g = 0; g < 4; g++) {
                    uint32_t bh[4];
                    ldm4(bh, w2B + (uint32_t)(g * 16 * W2_PITCH + kb * 16) * 2);
                    mma16816(acc2[g * 2],         ya0, bh[0], bh[1]);
                    mma16816(acc2[g * 2 + 1],     ya0, bh[2], bh[3]);
                    mma16816(acc2[8 + g * 2],     ya1, bh[0], bh[1]);
                    mma16816(acc2[8 + g * 2 + 1], ya1, bh[2], bh[3]);
                }
            }
        }

        // ---- end of i-phase: gate = sigmoid(acc2 + bi2) -> fp16 in X's h0 area; reset acc2 ----
        if (c == 7) {
            #pragma unroll
            for (int f = 0; f < 16; f++) {
                int m16 = f >> 3, g = (f >> 1) & 3, h = f & 1;
                int gcol = nh * 64 + g * 16 + h * 8 + 2 * cq;
                float z0 = bi2[gcol], z1 = bi2[gcol + 1];
                int rA2 = row0 + m16 * 16 + rql, rB2 = rA2 + 8;
                float g0 = 1.f / (1.f + __expf(-(acc2[f][0] + z0)));
                float g1 = 1.f / (1.f + __expf(-(acc2[f][1] + z1)));
                float g2 = 1.f / (1.f + __expf(-(acc2[f][2] + z0)));
                float g3 = 1.f / (1.f + __expf(-(acc2[f][3] + z1)));
                *(__half2*)(sm + OFF_X + (rA2 * X_PITCH + 128 + gcol) * 2) = __floats2half2_rn(g0, g1);
                *(__half2*)(sm + OFF_X + (rB2 * X_PITCH + 128 + gcol) * 2) = __floats2half2_rn(g2, g3);
                acc2[f][0] = acc2[f][1] = acc2[f][2] = acc2[f][3] = 0.f;
            }
        }
    }

    __syncthreads();   // all W1/W2 reads done before aliasing as scatter buffer

    // ---- Rv = gate * (jv + bj2) -> SMEM (128 x 132 f32 over W1B0..W2B1) ----
    float* rvb = (float*)(sm + OFF_W1B0);
    #pragma unroll
    for (int f = 0; f < 16; f++) {
        int m16 = f >> 3, g = (f >> 1) & 3, h = f & 1;
        int gcol = nh * 64 + g * 16 + h * 8 + 2 * cq;
        float z0 = bj2[gcol], z1 = bj2[gcol + 1];
        int rA2 = row0 + m16 * 16 + rql, rB2 = rA2 + 8;
        __half2 gA = *(__half2*)(sm + OFF_X + (rA2 * X_PITCH + 128 + gcol) * 2);
        __half2 gB = *(__half2*)(sm + OFF_X + (rB2 * X_PITCH + 128 + gcol) * 2);
        rvb[rA2 * RV_PITCH + gcol]     = __half2float(__low2half(gA))  * (acc2[f][0] + z0);
        rvb[rA2 * RV_PITCH + gcol + 1] = __half2float(__high2half(gA)) * (acc2[f][1] + z1);
        rvb[rB2 * RV_PITCH + gcol]     = __half2float(__low2half(gB))  * (acc2[f][2] + z0);
        rvb[rB2 * RV_PITCH + gcol + 1] = __half2float(__high2half(gB)) * (acc2[f][3] + z1);
    }
    __syncthreads();

    // ---- run-length merged scatter (graph_index sorted) ----
    {
        int col = tid & 127, rg = tid >> 7;   // rg in {0,1}, 64 rows each
        float sum = 0.f; int cur = -1;
        for (int r = rg * 64; r < rg * 64 + 64; r++) {
            int m = m0 + r;
            if (m >= M_NODES) break;
            int g = sgi[r];
            float v = rvb[r * RV_PITCH + col];
            if (g != cur) {
                if (cur >= 0) atomicAdd(&R[(size_t)cur * 128 + col], sum);
                cur = g; sum = v;
            } else sum += v;
        }
        if (cur >= 0) atomicAdd(&R[(size_t)cur * 128 + col], sum);
    }
}

// ---------------- launch ----------------
extern "C" void kernel_launch(void* const* d_in, const int* in_sizes, int n_in,
                              void* d_out, int out_size) {
    const float* h_T = (const float*)d_in[0];
    const float* h_0 = (const float*)d_in[1];
    const int*   gix = (const int*)d_in[2];
    const float* Wi1 = (const float*)d_in[3];
    const float* bi1 = (const float*)d_in[4];
    const float* Wi2 = (const float*)d_in[5];
    const float* bi2 = (const float*)d_in[6];
    const float* Wj1 = (const float*)d_in[7];
    const float* bj1 = (const float*)d_in[8];
    const float* Wj2 = (const float*)d_in[9];
    const float* bj2 = (const float*)d_in[10];
    float* R = (float*)d_out;

    cudaFuncSetAttribute(fused_kernel, cudaFuncAttributeMaxDynamicSharedMemorySize, SMEM_BYTES);

    int setup_elems = 512 * 256 + 512 * 128 + 2 * 128 * 512;   // >= NGRAPH*128
    setup_kernel<<<(setup_elems + 255) / 256, 256>>>(Wi1, Wj1, Wi2, Wj2, R);
    fused_kernel<<<NTILES, NT, SMEM_BYTES>>>(h_T, h_0, gix, bi1, bj1, bi2, bj2, R);
}

// round 17
// speedup vs baseline: 6.0801x; 1.0205x over previous
#include <cuda_runtime.h>
#include <cuda_fp16.h>
#include <cstdint>

#define M_NODES 200000
#define NGRAPH  1024
#define NT      256
#define BM      128
#define NTILES  ((M_NODES + BM - 1) / BM)   // 1563

// ---- SMEM layout (bytes) ----
#define OFF_X     0          // 128 x 264 half = 67584 (cols 0-127 hT, 128-255 h0 -> fp16 gate after i-phase)
#define X_PITCH   264
#define OFF_W1B0  67584      // 64 x 136 half = 17408 (double-buffered W1)
#define OFF_W1B1  84992
#define W1_PITCH  136
#define OFF_W2    102400     // 3 x (128 x 72 half = 18432): chunk c -> buffer c%3
#define W2SZ      18432
#define W2_PITCH  72
#define OFF_Y     157696     // 2 x (128 x 72 half = 18432): chunk c writes Y[c&1]
#define YSZ       18432
#define Y_PITCH   72
#define OFF_GI    194560     // 128 int
#define SMEM_BYTES 195072    // 1 CTA/SM
#define RV_PITCH  132        // fp32 scatter buffer aliased from OFF_W1B0 (128*132*4 = 67584, ends 135168 < OFF_Y)

// ---- pre-rounded fp16 weights, [n][k] row-major ----
__device__ __half g_w1i[512 * 256];
__device__ __half g_w1j[512 * 128];
__device__ __half g_w2i[128 * 512];
__device__ __half g_w2j[128 * 512];

__device__ __forceinline__ uint32_t smem_u32(const void* p) {
    uint32_t a;
    asm("{ .reg .u64 t; cvta.to.shared.u64 t, %1; cvt.u32.u64 %0, t; }" : "=r"(a) : "l"(p));
    return a;
}
__device__ __forceinline__ void ldm4(uint32_t r[4], uint32_t addr) {
    asm volatile("ldmatrix.sync.aligned.m8n8.x4.shared.b16 {%0,%1,%2,%3}, [%4];"
        : "=r"(r[0]), "=r"(r[1]), "=r"(r[2]), "=r"(r[3]) : "r"(addr));
}
__device__ __forceinline__ void mma16816(float d[4], const uint32_t a[4],
                                         uint32_t b0, uint32_t b1) {
    asm volatile("mma.sync.aligned.m16n8k16.row.col.f32.f16.f16.f32 "
        "{%0,%1,%2,%3}, {%4,%5,%6,%7}, {%8,%9}, {%0,%1,%2,%3};"
        : "+f"(d[0]), "+f"(d[1]), "+f"(d[2]), "+f"(d[3])
        : "r"(a[0]), "r"(a[1]), "r"(a[2]), "r"(a[3]), "r"(b0), "r"(b1));
}
__device__ __forceinline__ void cpasync16(uint32_t dst, const void* src) {
    asm volatile("cp.async.cg.shared.global [%0], [%1], 16;" :: "r"(dst), "l"(src) : "memory");
}

// ---------- setup: zero output + round weights to fp16, transpose to [n][k] ----------
__global__ void setup_kernel(const float* __restrict__ Wi1, const float* __restrict__ Wj1,
                             const float* __restrict__ Wi2, const float* __restrict__ Wj2,
                             float* __restrict__ R) {
    int idx = blockIdx.x * blockDim.x + threadIdx.x;
    if (idx < NGRAPH * 128) R[idx] = 0.0f;
    if (idx < 512 * 256) {
        int n = idx >> 8, k = idx & 255;
        g_w1i[idx] = __float2half(Wi1[(size_t)k * 512 + n]);
    } else if (idx < 512 * 256 + 512 * 128) {
        int j = idx - 512 * 256; int n = j >> 7, k = j & 127;
        g_w1j[j] = __float2half(Wj1[(size_t)k * 512 + n]);
    } else if (idx < 512 * 256 + 512 * 128 + 128 * 512) {
        int j = idx - 512 * 256 - 512 * 128; int n = j >> 9, k = j & 511;
        g_w2i[j] = __float2half(Wi2[(size_t)k * 128 + n]);
    } else if (idx < 512 * 256 + 512 * 128 + 2 * 128 * 512) {
        int j = idx - 512 * 256 - 512 * 128 - 128 * 512; int n = j >> 9, k = j & 511;
        g_w2j[j] = __float2half(Wj2[(size_t)k * 128 + n]);
    }
}

// stage unit u (0..23): W1 slice (+W2 on first slice of a chunk, into buffer c%3); always commit.
// u<16: chunk c=u>>1 (i-path), slice s=u&1.  u>=16: chunk c=u-8 (j-path), s=0.
__device__ __forceinline__ void issue_stage(int u, uint32_t su, int tid) {
    if (u < 24) {
        int c, s;
        if (u < 16) { c = u >> 1; s = u & 1; } else { c = u - 8; s = 0; }
        const bool ipath = (c < 8);
        const int kst = ipath ? 256 : 128;
        const __half* src1 = ipath ? (g_w1i + (size_t)c * 64 * 256 + s * 128)
                                   : (g_w1j + (size_t)(c - 8) * 64 * 128);
        uint32_t dst1 = su + ((u & 1) ? OFF_W1B1 : OFF_W1B0);
        #pragma unroll
        for (int j = 0; j < 4; j++) {
            int idx = tid + j * NT;
            int r = idx >> 4, q = idx & 15;
            cpasync16(dst1 + (uint32_t)(r * (W1_PITCH * 2) + q * 16),
                      src1 + (size_t)r * kst + q * 8);
        }
        if (s == 0) {
            const __half* src2 = (ipath ? g_w2i : g_w2j) + (c & 7) * 64;
            uint32_t dst2 = su + OFF_W2 + (uint32_t)((c % 3) * W2SZ);
            #pragma unroll
            for (int j = 0; j < 4; j++) {
                int idx = tid + j * NT;
                int r = idx >> 3, q = idx & 7;
                cpasync16(dst2 + (uint32_t)(r * (W2_PITCH * 2) + q * 16),
                          src2 + (size_t)r * 512 + q * 8);
            }
        }
    }
    asm volatile("cp.async.commit_group;" ::: "memory");
}

// ---------- fused MLP + gate + segment-sum ----------
// 8 warps: rowgrp = wid&3 (32 rows), nh = wid>>2 (MMA1: 32 hidden cols; MMA2: 64 out cols).
// Phase-staggered: chunk c's slice-0 window runs MMA1(c) and MMA2(c-1); even warps
// order [MMA1,MMA2], odd warps [MMA2,MMA1] so LDSM and HMMA phases interleave per SMSP.
__global__ __launch_bounds__(NT, 1)
void fused_kernel(const float* __restrict__ hT, const float* __restrict__ h0,
                  const int* __restrict__ gidx,
                  const float* __restrict__ bi1, const float* __restrict__ bj1,
                  const float* __restrict__ bi2, const float* __restrict__ bj2,
                  float* __restrict__ R) {
    extern __shared__ char sm[];
    const uint32_t su = smem_u32(sm);
    const int tid = threadIdx.x;
    const int wid = tid >> 5, lane = tid & 31;
    const int rowgrp = wid & 3, nh = wid >> 2;
    const int row0 = rowgrp * 32;
    const int m0 = blockIdx.x * BM;
    const int cq = lane & 3;
    const int rql = lane >> 2;

    int* sgi = (int*)(sm + OFF_GI);
    if (tid < BM) { int m = m0 + tid; sgi[tid] = (m < M_NODES) ? gidx[m] : 0; }

    // ---- stage X = [hT|h0] fp16 into SMEM (128 rows, 2 threads/row) ----
    {
        int m = m0 + (tid >> 1);
        int hf = tid & 1;
        bool valid = (m < M_NODES);
        __half2* xrow = (__half2*)(sm + OFF_X) + (size_t)(tid >> 1) * (X_PITCH / 2);
        #pragma unroll
        for (int src = 0; src < 2; src++) {
            const float* p = (src ? h0 : hT) + (size_t)m * 128 + hf * 64;
            int hib = src * 128 + hf * 64;
            #pragma unroll
            for (int q = 0; q < 16; q++) {
                float4 v = valid ? ((const float4*)p)[q] : make_float4(0.f, 0.f, 0.f, 0.f);
                xrow[(hib >> 1) + 2 * q]     = __floats2half2_rn(v.x, v.y);
                xrow[(hib >> 1) + 2 * q + 1] = __floats2half2_rn(v.z, v.w);
            }
        }
    }

    issue_stage(0, su, tid);
    __syncthreads();   // X (and sgi) visible to all warps

    // ldmatrix lane address components
    const int arow0 = row0 + (lane & 15);
    const int acolo = (lane >> 4) << 3;
    const int bn = (lane & 7) + ((lane >> 4) << 3);
    const int bk = ((lane >> 3) & 1) << 3;
    const uint32_t xA0 = su + (uint32_t)(arow0 * X_PITCH) * 2;
    const uint32_t xA1 = su + (uint32_t)((arow0 + 16) * X_PITCH) * 2;
    const uint32_t yA0 = su + OFF_Y + (uint32_t)(arow0 * Y_PITCH + acolo) * 2;          // Y buf0 read base
    const uint32_t yA1 = su + OFF_Y + (uint32_t)((arow0 + 16) * Y_PITCH + acolo) * 2;
    const uint32_t w1b0 = su + OFF_W1B0 + (uint32_t)((nh * 32 + bn) * W1_PITCH + bk) * 2;
    const uint32_t w1b1 = su + OFF_W1B1 + (uint32_t)((nh * 32 + bn) * W1_PITCH + bk) * 2;
    const uint32_t w2base = su + OFF_W2 + (uint32_t)((nh * 64 + bn) * W2_PITCH + bk) * 2; // + (c%3)*W2SZ

    float acc2[16][4];
    #pragma unroll
    for (int t = 0; t < 16; t++)
        #pragma unroll
        for (int q = 0; q < 4; q++) acc2[t][q] = 0.f;

// ---- MMA1 slice body (uses wB, s from enclosing scope) ----
#define MMA1SLICE(S, WB) do {                                                     \
    _Pragma("unroll")                                                             \
    for (int k16 = 0; k16 < 8; k16++) {                                           \
        uint32_t a0[4], a1[4], b0[4], b1[4];                                      \
        uint32_t coff = (uint32_t)((S) * 128 + k16 * 16 + acolo) * 2;             \
        ldm4(a0, xA0 + coff);                                                     \
        ldm4(a1, xA1 + coff);                                                     \
        ldm4(b0, (WB) + (uint32_t)(k16 * 16) * 2);                                \
        ldm4(b1, (WB) + (uint32_t)(16 * W1_PITCH + k16 * 16) * 2);                \
        mma16816(acc1[0], a0, b0[0], b0[1]);                                      \
        mma16816(acc1[1], a0, b0[2], b0[3]);                                      \
        mma16816(acc1[2], a0, b1[0], b1[1]);                                      \
        mma16816(acc1[3], a0, b1[2], b1[3]);                                      \
        mma16816(acc1[4], a1, b0[0], b0[1]);                                      \
        mma16816(acc1[5], a1, b0[2], b0[3]);                                      \
        mma16816(acc1[6], a1, b1[0], b1[1]);                                      \
        mma16816(acc1[7], a1, b1[2], b1[3]);                                      \
    }                                                                             \
} while (0)

// ---- MMA2 for chunk CP (reads W2 buf CP%3, Y buf CP&1); includes gate at CP==7 ----
#define MMA2PREV(CP) do {                                                         \
    const uint32_t _w2B = w2base + (uint32_t)(((CP) % 3) * W2SZ);                 \
    const uint32_t _yb = (uint32_t)(((CP) & 1) * YSZ);                            \
    _Pragma("unroll")                                                             \
    for (int kb = 0; kb < 4; kb++) {                                              \
        uint32_t ya0[4], ya1[4];                                                  \
        ldm4(ya0, yA0 + _yb + (uint32_t)(kb * 16) * 2);                           \
        ldm4(ya1, yA1 + _yb + (uint32_t)(kb * 16) * 2);                           \
        _Pragma("unroll")                                                         \
        for (int g = 0; g < 4; g++) {                                             \
            uint32_t bh[4];                                                       \
            ldm4(bh, _w2B + (uint32_t)(g * 16 * W2_PITCH + kb * 16) * 2);         \
            mma16816(acc2[g * 2],         ya0, bh[0], bh[1]);                     \
            mma16816(acc2[g * 2 + 1],     ya0, bh[2], bh[3]);                     \
            mma16816(acc2[8 + g * 2],     ya1, bh[0], bh[1]);                     \
            mma16816(acc2[8 + g * 2 + 1], ya1, bh[2], bh[3]);                     \
        }                                                                         \
    }                                                                             \
    if ((CP) == 7) {                                                              \
        _Pragma("unroll")                                                         \
        for (int f = 0; f < 16; f++) {                                            \
            int m16 = f >> 3, g = (f >> 1) & 3, h = f & 1;                        \
            int gcol = nh * 64 + g * 16 + h * 8 + 2 * cq;                         \
            float z0 = bi2[gcol], z1 = bi2[gcol + 1];                             \
            int rA2 = row0 + m16 * 16 + rql, rB2 = rA2 + 8;                       \
            float g0 = 1.f / (1.f + __expf(-(acc2[f][0] + z0)));                  \
            float g1 = 1.f / (1.f + __expf(-(acc2[f][1] + z1)));                  \
            float g2 = 1.f / (1.f + __expf(-(acc2[f][2] + z0)));                  \
            float g3 = 1.f / (1.f + __expf(-(acc2[f][3] + z1)));                  \
            *(__half2*)(sm + OFF_X + (rA2 * X_PITCH + 128 + gcol) * 2) = __floats2half2_rn(g0, g1); \
            *(__half2*)(sm + OFF_X + (rB2 * X_PITCH + 128 + gcol) * 2) = __floats2half2_rn(g2, g3); \
            acc2[f][0] = acc2[f][1] = acc2[f][2] = acc2[f][3] = 0.f;              \
        }                                                                         \
    }                                                                             \
} while (0)

    int u = 0;
    #pragma unroll 1
    for (int c = 0; c < 16; c++) {
        const bool ipath = (c < 8);
        const int c8 = c & 7;

        float acc1[8][4];   // [m16*4 + n16g*2 + h]
        #pragma unroll
        for (int t = 0; t < 8; t++)
            #pragma unroll
            for (int q = 0; q < 4; q++) acc1[t][q] = 0.f;

        const int nsl = ipath ? 2 : 1;
        #pragma unroll 1
        for (int s = 0; s < nsl; s++, u++) {
            asm volatile("cp.async.wait_group 0;" ::: "memory");
            __syncthreads();
            issue_stage(u + 1, su, tid);

            const uint32_t wB = (u & 1) ? w1b1 : w1b0;
            if (s == 0 && c > 0) {
                int cp = c - 1;
                if (wid & 1) { MMA2PREV(cp); MMA1SLICE(0, wB); }
                else         { MMA1SLICE(0, wB); MMA2PREV(cp); }
            } else {
                MMA1SLICE(s, wB);
            }
        }

        // ---- epilogue: bias + ReLU + fp16 round -> Y[c&1] (warp: 32 rows x 32 cols) ----
        {
            const float* bsrc = ipath ? bi1 : bj1;
            const uint32_t ybW = (uint32_t)((c & 1) * YSZ);
            #pragma unroll
            for (int f = 0; f < 8; f++) {
                int m16 = f >> 2, n16g = (f >> 1) & 1, h = f & 1;
                int col = nh * 32 + n16g * 16 + h * 8 + 2 * cq;
                float bz0 = bsrc[c8 * 64 + col], bz1 = bsrc[c8 * 64 + col + 1];
                int rA2 = row0 + m16 * 16 + rql, rB2 = rA2 + 8;
                float x0 = fmaxf(acc1[f][0] + bz0, 0.f);
                float x1 = fmaxf(acc1[f][1] + bz1, 0.f);
                float x2 = fmaxf(acc1[f][2] + bz0, 0.f);
                float x3 = fmaxf(acc1[f][3] + bz1, 0.f);
                *(__half2*)(sm + OFF_Y + ybW + (rA2 * Y_PITCH + col) * 2) = __floats2half2_rn(x0, x1);
                *(__half2*)(sm + OFF_Y + ybW + (rB2 * Y_PITCH + col) * 2) = __floats2half2_rn(x2, x3);
            }
        }
        __syncthreads();   // Y[c&1] published; also fences Y[(c-1)&1] readers before next overwrite
    }

    // ---- final chunk's layer-2 ----
    MMA2PREV(15);
    __syncthreads();   // all W1/W2 reads done before aliasing as scatter buffer

    // ---- Rv = gate * (jv + bj2) -> SMEM (128 x 132 f32 from OFF_W1B0) ----
    float* rvb = (float*)(sm + OFF_W1B0);
    #pragma unroll
    for (int f = 0; f < 16; f++) {
        int m16 = f >> 3, g = (f >> 1) & 3, h = f & 1;
        int gcol = nh * 64 + g * 16 + h * 8 + 2 * cq;
        float z0 = bj2[gcol], z1 = bj2[gcol + 1];
        int rA2 = row0 + m16 * 16 + rql, rB2 = rA2 + 8;
        __half2 gA = *(__half2*)(sm + OFF_X + (rA2 * X_PITCH + 128 + gcol) * 2);
        __half2 gB = *(__half2*)(sm + OFF_X + (rB2 * X_PITCH + 128 + gcol) * 2);
        rvb[rA2 * RV_PITCH + gcol]     = __half2float(__low2half(gA))  * (acc2[f][0] + z0);
        rvb[rA2 * RV_PITCH + gcol + 1] = __half2float(__high2half(gA)) * (acc2[f][1] + z1);
        rvb[rB2 * RV_PITCH + gcol]     = __half2float(__low2half(gB))  * (acc2[f][2] + z0);
        rvb[rB2 * RV_PITCH + gcol + 1] = __half2float(__high2half(gB)) * (acc2[f][3] + z1);
    }
    __syncthreads();

    // ---- run-length merged scatter (graph_index sorted) ----
    {
        int col = tid & 127, rg = tid >> 7;   // rg in {0,1}, 64 rows each
        float sum = 0.f; int cur = -1;
        for (int r = rg * 64; r < rg * 64 + 64; r++) {
            int m = m0 + r;
            if (m >= M_NODES) break;
            int g = sgi[r];
            float v = rvb[r * RV_PITCH + col];
            if (g != cur) {
                if (cur >= 0) atomicAdd(&R[(size_t)cur * 128 + col], sum);
                cur = g; sum = v;
            } else sum += v;
        }
        if (cur >= 0) atomicAdd(&R[(size_t)cur * 128 + col], sum);
    }
#undef MMA1SLICE
#undef MMA2PREV
}

// ---------------- launch ----------------
extern "C" void kernel_launch(void* const* d_in, const int* in_sizes, int n_in,
                              void* d_out, int out_size) {
    const float* h_T = (const float*)d_in[0];
    const float* h_0 = (const float*)d_in[1];
    const int*   gix = (const int*)d_in[2];
    const float* Wi1 = (const float*)d_in[3];
    const float* bi1 = (const float*)d_in[4];
    const float* Wi2 = (const float*)d_in[5];
    const float* bi2 = (const float*)d_in[6];
    const float* Wj1 = (const float*)d_in[7];
    const float* bj1 = (const float*)d_in[8];
    const float* Wj2 = (const float*)d_in[9];
    const float* bj2 = (const float*)d_in[10];
    float* R = (float*)d_out;

    cudaFuncSetAttribute(fused_kernel, cudaFuncAttributeMaxDynamicSharedMemorySize, SMEM_BYTES);

    int setup_elems = 512 * 256 + 512 * 128 + 2 * 128 * 512;   // >= NGRAPH*128
    setup_kernel<<<(setup_elems + 255) / 256, 256>>>(Wi1, Wj1, Wi2, Wj2, R);
    fused_kernel<<<NTILES, NT, SMEM_BYTES>>>(h_T, h_0, gix, bi1, bj1, bi2, bj2, R);
}